// round 5
// baseline (speedup 1.0000x reference)
#include <cuda_runtime.h>

#define N_TOK   16384      // B*T = 8*2048
#define EDIM    1024
#define DHEAD   32
#define MFEAT   256

typedef unsigned long long u64;

__device__ __forceinline__ u64 fma2(u64 a, u64 b, u64 c) {
    u64 d;
    asm("fma.rn.f32x2 %0, %1, %2, %3;" : "=l"(d) : "l"(a), "l"(b), "l"(c));
    return d;
}
__device__ __forceinline__ float2 u2f(u64 v) {
    float2 f;
    asm("mov.b64 {%0, %1}, %2;" : "=f"(f.x), "=f"(f.y) : "l"(v));
    return f;
}

// scratch (allocation-free rule: __device__ globals)
__device__ float g_z[N_TOK * DHEAD];   // z = q+k (bias included)
__device__ float g_s[N_TOK];           // s = 0.5*(|q|^2+|k|^2)

// ---------------------------------------------------------------------------
// Kernel 1: fused q/k projection with packed f32x2 FMAs.
//   C[64 tokens x 64 cols] = x_tile[64,1024] @ [Wq | Wk][1024,64]
//   Bs holds each column value DUPLICATED ([b,b] pairs) so FFMA2 needs no packs.
//   A pairs are adjacent rows (M-packing). 16 FFMA2 + 4 LDS.128 per k-step.
// ---------------------------------------------------------------------------
__global__ __launch_bounds__(128) void proj_kernel(
    const float* __restrict__ x,
    const float* __restrict__ Wq, const float* __restrict__ bq,
    const float* __restrict__ Wk, const float* __restrict__ bk)
{
    // As: [2][32][64] = 16KB ; Bs(dup): [2][32][128] = 32KB ; total 48KB exactly.
    __shared__ __align__(16) float smem_raw[2*32*64 + 2*32*128];
    float (*As)[32][64]  = reinterpret_cast<float(*)[32][64]>(smem_raw);
    float (*Bs)[32][128] = reinterpret_cast<float(*)[32][128]>(smem_raw + 2*32*64);
    // Ps aliases As (dead after mainloop): 16*64 floats = 4KB
    float (*Ps)[64] = reinterpret_cast<float(*)[64]>(smem_raw);

    const int tid  = threadIdx.x;
    const int tr   = tid & 7;         // row group: rows tr*8 .. tr*8+7
    const int tc   = tid >> 3;        // col group 0..15 -> cols {2tc,2tc+1} of q and k
    const int row0 = blockIdx.x * 64;

    // acc[row-pair p][j]: j = 0:q_col0, 1:q_col1, 2:k_col0, 3:k_col1
    u64 acc[4][4];
    #pragma unroll
    for (int p = 0; p < 4; p++)
        acc[p][0] = acc[p][1] = acc[p][2] = acc[p][3] = 0ull;

    const int NT = EDIM / 32;

    // ---- stage tile 0 ----
    #pragma unroll
    for (int i = 0; i < 4; i++) {
        int idx = i * 128 + tid;
        int xr = idx >> 3, kq = idx & 7;
        float4 v = *(const float4*)&x[(size_t)(row0 + xr) * EDIM + kq * 4];
        As[0][kq * 4 + 0][xr] = v.x; As[0][kq * 4 + 1][xr] = v.y;
        As[0][kq * 4 + 2][xr] = v.z; As[0][kq * 4 + 3][xr] = v.w;
        int k = idx >> 4, c4 = idx & 15;
        float4 wv;
        int base;
        if (c4 < 8) { wv = *(const float4*)&Wq[(size_t)k * 32 + c4 * 4]; base = c4 * 8; }
        else        { wv = *(const float4*)&Wk[(size_t)k * 32 + (c4 - 8) * 4]; base = 64 + (c4 - 8) * 8; }
        *(float4*)&Bs[0][k][base]     = make_float4(wv.x, wv.x, wv.y, wv.y);
        *(float4*)&Bs[0][k][base + 4] = make_float4(wv.z, wv.z, wv.w, wv.w);
    }
    __syncthreads();

    for (int t = 0; t < NT; t++) {
        float4 xa[4], wa[4];
        if (t + 1 < NT) {
            int kt = (t + 1) * 32;
            #pragma unroll
            for (int i = 0; i < 4; i++) {
                int idx = i * 128 + tid;
                int xr = idx >> 3, kq = idx & 7;
                xa[i] = *(const float4*)&x[(size_t)(row0 + xr) * EDIM + kt + kq * 4];
                int k = idx >> 4, c4 = idx & 15;
                if (c4 < 8) wa[i] = *(const float4*)&Wq[(size_t)(kt + k) * 32 + c4 * 4];
                else        wa[i] = *(const float4*)&Wk[(size_t)(kt + k) * 32 + (c4 - 8) * 4];
            }
        }
        const int buf = t & 1;
        #pragma unroll
        for (int k = 0; k < 32; k++) {
            const ulonglong2* Ap = (const ulonglong2*)&As[buf][k][tr * 8];
            ulonglong2 a01 = Ap[0];                                     // row pairs (0,1),(2,3)
            ulonglong2 a23 = Ap[1];                                     // row pairs (4,5),(6,7)
            ulonglong2 bqp = *(const ulonglong2*)&Bs[buf][k][4 * tc];        // (bq0,bq0),(bq1,bq1)
            ulonglong2 bkp = *(const ulonglong2*)&Bs[buf][k][64 + 4 * tc];   // (bk0,bk0),(bk1,bk1)
            u64 ap[4] = {a01.x, a01.y, a23.x, a23.y};
            u64 bb[4] = {bqp.x, bqp.y, bkp.x, bkp.y};
            #pragma unroll
            for (int p = 0; p < 4; p++) {
                acc[p][0] = fma2(ap[p], bb[0], acc[p][0]);
                acc[p][1] = fma2(ap[p], bb[1], acc[p][1]);
                acc[p][2] = fma2(ap[p], bb[2], acc[p][2]);
                acc[p][3] = fma2(ap[p], bb[3], acc[p][3]);
            }
        }
        if (t + 1 < NT) {
            const int nb = (t + 1) & 1;
            #pragma unroll
            for (int i = 0; i < 4; i++) {
                int idx = i * 128 + tid;
                int xr = idx >> 3, kq = idx & 7;
                As[nb][kq * 4 + 0][xr] = xa[i].x; As[nb][kq * 4 + 1][xr] = xa[i].y;
                As[nb][kq * 4 + 2][xr] = xa[i].z; As[nb][kq * 4 + 3][xr] = xa[i].w;
                int k = idx >> 4, c4 = idx & 15;
                int base = (c4 < 8) ? c4 * 8 : 64 + (c4 - 8) * 8;
                *(float4*)&Bs[nb][k][base]     = make_float4(wa[i].x, wa[i].x, wa[i].y, wa[i].y);
                *(float4*)&Bs[nb][k][base + 4] = make_float4(wa[i].z, wa[i].z, wa[i].w, wa[i].w);
            }
        }
        __syncthreads();
    }

    // epilogue: z = q+k (with biases), partial zsqr.  (As is dead; Ps aliases it.)
    const float bq0 = bq[2 * tc], bq1 = bq[2 * tc + 1];
    const float bk0 = bk[2 * tc], bk1 = bk[2 * tc + 1];
    #pragma unroll
    for (int p = 0; p < 4; p++) {
        float2 cq0 = u2f(acc[p][0]);   // q col0, rows (2p, 2p+1)
        float2 cq1 = u2f(acc[p][1]);
        float2 ck0 = u2f(acc[p][2]);
        float2 ck1 = u2f(acc[p][3]);
        #pragma unroll
        for (int h = 0; h < 2; h++) {
            int row = tr * 8 + 2 * p + h;
            int tok = row0 + row;
            float q0 = (h ? cq0.y : cq0.x) + bq0;
            float q1 = (h ? cq1.y : cq1.x) + bq1;
            float k0 = (h ? ck0.y : ck0.x) + bk0;
            float k1 = (h ? ck1.y : ck1.x) + bk1;
            *(float2*)&g_z[(size_t)tok * DHEAD + 2 * tc] = make_float2(q0 + k0, q1 + k1);
            Ps[tc][row] = q0 * q0 + q1 * q1 + k0 * k0 + k1 * k1;
        }
    }
    __syncthreads();
    if (tid < 64) {
        float s = 0.f;
        #pragma unroll
        for (int j = 0; j < 16; j++) s += Ps[j][tid];
        g_s[row0 + tid] = 0.5f * s;
    }
}

// ---------------------------------------------------------------------------
// Kernel 2: R[t,m] = 0.5*(exp(u-s) + exp(-u-s)),  u = z[t]·w[m]
// 256 threads (one per m, w_m packed in 16 u64 regs), 32 tokens/block,
// dot product via 16 FFMA2 with two accumulators.
// ---------------------------------------------------------------------------
__global__ __launch_bounds__(256) void feat_kernel(
    const float* __restrict__ w, float* __restrict__ out)
{
    __shared__ __align__(16) float zs[32][32];
    __shared__ float ss[32];
    const int m  = threadIdx.x;
    const int t0 = blockIdx.x * 32;

    u64 wp[16];
    #pragma unroll
    for (int j = 0; j < 4; j++) {
        ulonglong2 v = *(const ulonglong2*)&w[(size_t)m * DHEAD + j * 8];
        wp[j * 4 + 0] = v.x; wp[j * 4 + 1] = v.y;
        ulonglong2 v2 = *(const ulonglong2*)&w[(size_t)m * DHEAD + j * 8 + 4];
        wp[j * 4 + 2] = v2.x; wp[j * 4 + 3] = v2.y;
    }
    {
        int r = m >> 3, q = m & 7;   // 256 float4 = 32 tokens * 8 float4
        *(float4*)&zs[r][q * 4] = *(const float4*)&g_z[(size_t)(t0 + r) * DHEAD + q * 4];
        if (m < 32) ss[m] = g_s[t0 + m];
    }
    __syncthreads();

    #pragma unroll 4
    for (int tt = 0; tt < 32; tt++) {
        u64 acc0 = 0ull, acc1 = 0ull;
        #pragma unroll
        for (int j = 0; j < 4; j++) {
            ulonglong2 z0 = *(const ulonglong2*)&zs[tt][j * 8];
            ulonglong2 z1 = *(const ulonglong2*)&zs[tt][j * 8 + 4];
            acc0 = fma2(z0.x, wp[j * 4 + 0], acc0);
            acc1 = fma2(z0.y, wp[j * 4 + 1], acc1);
            acc0 = fma2(z1.x, wp[j * 4 + 2], acc0);
            acc1 = fma2(z1.y, wp[j * 4 + 3], acc1);
        }
        float2 f0 = u2f(acc0);
        float2 f1 = u2f(acc1);
        float u = (f0.x + f0.y) + (f1.x + f1.y);
        float s = ss[tt];
        float r = 0.5f * (__expf(u - s) + __expf(-u - s));
        out[(size_t)(t0 + tt) * MFEAT + m] = r;
    }
}

extern "C" void kernel_launch(void* const* d_in, const int* in_sizes, int n_in,
                              void* d_out, int out_size)
{
    const float* x  = (const float*)d_in[0];
    const float* Wq = (const float*)d_in[1];
    const float* bq = (const float*)d_in[2];
    const float* Wk = (const float*)d_in[3];
    const float* bk = (const float*)d_in[4];
    // d_in[5], d_in[6] = Wv, bv: unused (reference discards v)
    const float* w  = (const float*)d_in[7];
    float* out = (float*)d_out;

    proj_kernel<<<N_TOK / 64, 128>>>(x, Wq, bq, Wk, bk);
    feat_kernel<<<N_TOK / 32, 256>>>(w, out);
}

// round 7
// speedup vs baseline: 2.8007x; 2.8007x over previous
#include <cuda_runtime.h>
#include <cuda_bf16.h>
#include <cstdint>

#define N_TOK   16384      // B*T
#define EDIM    1024
#define DHEAD   32
#define MFEAT   256

typedef unsigned long long u64;

// ---------------- scratch (__device__ globals; no allocation) ----------------
__device__ float g_z[N_TOK * DHEAD];          // z = q+k (bias incl.)
__device__ float g_s[N_TOK];                  // 0.5*(|q|^2+|k|^2)
// W combined [64 n][1024 k] bf16 hi/lo, stored per 64-K chunk, 16B-chunk swizzled:
// element (c, n, kk) at [c*4096 + n*64 + ((kk/8 ^ (n&7))*8) + (kk&7)]
__device__ __nv_bfloat16 W_hi_g[16 * 64 * 64];
__device__ __nv_bfloat16 W_lo_g[16 * 64 * 64];

__device__ __forceinline__ uint32_t smem_u32(const void* p) {
    uint32_t a;
    asm("{ .reg .u64 t; cvta.to.shared.u64 t, %1; cvt.u32.u64 %0, t; }" : "=r"(a) : "l"(p));
    return a;
}
__device__ __forceinline__ void ldsm_x4(uint32_t& r0, uint32_t& r1, uint32_t& r2, uint32_t& r3, uint32_t a) {
    asm volatile("ldmatrix.sync.aligned.m8n8.x4.shared.b16 {%0,%1,%2,%3}, [%4];"
                 : "=r"(r0), "=r"(r1), "=r"(r2), "=r"(r3) : "r"(a));
}
__device__ __forceinline__ void ldsm_x2(uint32_t& r0, uint32_t& r1, uint32_t a) {
    asm volatile("ldmatrix.sync.aligned.m8n8.x2.shared.b16 {%0,%1}, [%2];"
                 : "=r"(r0), "=r"(r1) : "r"(a));
}
__device__ __forceinline__ void mma_bf16(float* c, const uint32_t* a, uint32_t b0, uint32_t b1) {
    asm volatile("mma.sync.aligned.m16n8k16.row.col.f32.bf16.bf16.f32 "
                 "{%0,%1,%2,%3}, {%4,%5,%6,%7}, {%8,%9}, {%0,%1,%2,%3};"
                 : "+f"(c[0]), "+f"(c[1]), "+f"(c[2]), "+f"(c[3])
                 : "r"(a[0]), "r"(a[1]), "r"(a[2]), "r"(a[3]), "r"(b0), "r"(b1));
}
__device__ __forceinline__ void cvtpair(float x, float y, uint32_t& h, uint32_t& l) {
    __nv_bfloat162 hh = __float22bfloat162_rn(make_float2(x, y));
    float2 f = __bfloat1622float2(hh);
    __nv_bfloat162 ll = __float22bfloat162_rn(make_float2(x - f.x, y - f.y));
    h = *(uint32_t*)&hh;
    l = *(uint32_t*)&ll;
}

// ---------------- kernel 0: W -> bf16 hi/lo, chunk-swizzled ------------------
__global__ __launch_bounds__(256) void wprep_kernel(
    const float* __restrict__ Wq, const float* __restrict__ Wk)
{
    const int c   = blockIdx.x >> 3;    // K-chunk 0..15
    const int seg = blockIdx.x & 7;
    #pragma unroll
    for (int i = 0; i < 2; i++) {
        int idx = seg * 512 + i * 256 + threadIdx.x;   // 0..4095 within chunk
        int n  = idx >> 6;                              // 0..63 (q dims 0-31, k dims 32-63)
        int kk = idx & 63;
        int k  = c * 64 + kk;
        float v = (n < 32) ? Wq[(size_t)k * 32 + n] : Wk[(size_t)k * 32 + (n - 32)];
        __nv_bfloat16 h = __float2bfloat16(v);
        __nv_bfloat16 l = __float2bfloat16(v - __bfloat162float(h));
        int pos = c * 4096 + n * 64 + (((kk >> 3) ^ (n & 7)) << 3) + (kk & 7);
        W_hi_g[pos] = h;
        W_lo_g[pos] = l;
    }
}

// ---------------- kernel 1: mma.sync bf16 3-pass projection ------------------
// CTA: 128 rows x 64 cols (q||k). 8 warps, each M=16 x N=64.
__global__ __launch_bounds__(256, 1) void gemm_kernel(
    const float* __restrict__ x,
    const float* __restrict__ bq, const float* __restrict__ bk)
{
    __shared__ __align__(16) __nv_bfloat16 Ahi[128 * 64];   // 16KB
    __shared__ __align__(16) __nv_bfloat16 Alo[128 * 64];   // 16KB
    __shared__ __align__(16) __nv_bfloat16 Bhi[64 * 64];    // 8KB
    __shared__ __align__(16) __nv_bfloat16 Blo[64 * 64];    // 8KB

    const int tid = threadIdx.x;
    const int wid = tid >> 5, lid = tid & 31;
    const int row0 = blockIdx.x * 128;

    const uint32_t sAh = smem_u32(Ahi), sAl = smem_u32(Alo);
    const uint32_t sBh = smem_u32(Bhi), sBl = smem_u32(Blo);

    float acc[8][4];
    #pragma unroll
    for (int j = 0; j < 8; j++)
        acc[j][0] = acc[j][1] = acc[j][2] = acc[j][3] = 0.f;

    // conversion-writer indices (4 chunks of 8 floats per thread)
    int cr[4], ccc[4];
    #pragma unroll
    for (int i = 0; i < 4; i++) {
        int idx = i * 256 + tid;
        cr[i] = idx >> 3;           // row 0..127
        ccc[i] = idx & 7;           // 16B-chunk 0..7
    }
    // A ldmatrix lane geometry
    const int i4   = lid >> 3;                                  // 0..3 quadrant
    const int arow = wid * 16 + ((i4 & 1) << 3) + (lid & 7);
    const int l7   = lid & 7;
    const int achunk_add = (i4 >> 1);                           // 0 or 1
    // B ldmatrix lane geometry (x2: lanes 0-15 meaningful, replicate pattern)
    const int b_i  = (lid >> 3) & 1;

    // ---- prefetch chunk 0 ----
    float4 xa[4][2];
    uint4 bsh[2], bsl[2];
    #pragma unroll
    for (int i = 0; i < 4; i++) {
        const float4* p = (const float4*)&x[(size_t)(row0 + cr[i]) * EDIM + ccc[i] * 8];
        xa[i][0] = p[0]; xa[i][1] = p[1];
    }
    #pragma unroll
    for (int i = 0; i < 2; i++) {
        int idx = i * 256 + tid;
        bsh[i] = ((const uint4*)W_hi_g)[idx];
        bsl[i] = ((const uint4*)W_lo_g)[idx];
    }

    #pragma unroll 1
    for (int c = 0; c < 16; c++) {
        // ---- store staged chunk into smem (swizzled) ----
        #pragma unroll
        for (int i = 0; i < 4; i++) {
            uint4 H, L;
            cvtpair(xa[i][0].x, xa[i][0].y, H.x, L.x);
            cvtpair(xa[i][0].z, xa[i][0].w, H.y, L.y);
            cvtpair(xa[i][1].x, xa[i][1].y, H.z, L.z);
            cvtpair(xa[i][1].z, xa[i][1].w, H.w, L.w);
            uint32_t off = (uint32_t)(cr[i] * 128 + ((ccc[i] ^ (cr[i] & 7)) << 4));
            *(uint4*)((char*)Ahi + off) = H;
            *(uint4*)((char*)Alo + off) = L;
        }
        #pragma unroll
        for (int i = 0; i < 2; i++) {
            int idx = i * 256 + tid;
            ((uint4*)Bhi)[idx] = bsh[i];
            ((uint4*)Blo)[idx] = bsl[i];
        }
        // ---- prefetch chunk c+1 (hidden under mma phase) ----
        if (c < 15) {
            #pragma unroll
            for (int i = 0; i < 4; i++) {
                const float4* p = (const float4*)&x[(size_t)(row0 + cr[i]) * EDIM + (c + 1) * 64 + ccc[i] * 8];
                xa[i][0] = p[0]; xa[i][1] = p[1];
            }
            #pragma unroll
            for (int i = 0; i < 2; i++) {
                int idx = i * 256 + tid;
                bsh[i] = ((const uint4*)W_hi_g)[(c + 1) * 512 + idx];
                bsl[i] = ((const uint4*)W_lo_g)[(c + 1) * 512 + idx];
            }
        }
        __syncthreads();
        // ---- MMA phase: 4 k16-groups x 8 n-tiles x 3 passes ----
        #pragma unroll
        for (int gk = 0; gk < 4; gk++) {
            uint32_t ah[4], al[4];
            uint32_t aoff = (uint32_t)(arow * 128 + (((2 * gk + achunk_add) ^ l7) << 4));
            ldsm_x4(ah[0], ah[1], ah[2], ah[3], sAh + aoff);
            ldsm_x4(al[0], al[1], al[2], al[3], sAl + aoff);
            #pragma unroll
            for (int j = 0; j < 8; j++) {
                int brow = 8 * j + l7;
                uint32_t boff = (uint32_t)(brow * 128 + (((2 * gk + b_i) ^ l7) << 4));
                uint32_t bh0, bh1, bl0, bl1;
                ldsm_x2(bh0, bh1, sBh + boff);
                ldsm_x2(bl0, bl1, sBl + boff);
                mma_bf16(acc[j], ah, bh0, bh1);
                mma_bf16(acc[j], ah, bl0, bl1);
                mma_bf16(acc[j], al, bh0, bh1);
            }
        }
        __syncthreads();
    }

    // ---- epilogue: z = q+k (+biases), s = 0.5*sum(q^2+k^2) ----
    const int g = lid >> 2, t = lid & 3;
    const int rA = row0 + wid * 16 + g;       // row for c0,c1
    const int rB = rA + 8;                    // row for c2,c3
    float s0 = 0.f, s1 = 0.f;
    #pragma unroll
    for (int j = 0; j < 4; j++) {
        int col = 8 * j + 2 * t;              // 0..31
        float2 bq2 = *(const float2*)&bq[col];
        float2 bk2 = *(const float2*)&bk[col];
        float q00 = acc[j][0] + bq2.x, q01 = acc[j][1] + bq2.y;
        float k00 = acc[j + 4][0] + bk2.x, k01 = acc[j + 4][1] + bk2.y;
        float q10 = acc[j][2] + bq2.x, q11 = acc[j][3] + bq2.y;
        float k10 = acc[j + 4][2] + bk2.x, k11 = acc[j + 4][3] + bk2.y;
        *(float2*)&g_z[(size_t)rA * DHEAD + col] = make_float2(q00 + k00, q01 + k01);
        *(float2*)&g_z[(size_t)rB * DHEAD + col] = make_float2(q10 + k10, q11 + k11);
        s0 += q00 * q00 + q01 * q01 + k00 * k00 + k01 * k01;
        s1 += q10 * q10 + q11 * q11 + k10 * k10 + k11 * k11;
    }
    s0 += __shfl_xor_sync(0xffffffffu, s0, 1);
    s0 += __shfl_xor_sync(0xffffffffu, s0, 2);
    s1 += __shfl_xor_sync(0xffffffffu, s1, 1);
    s1 += __shfl_xor_sync(0xffffffffu, s1, 2);
    if (t == 0) {
        g_s[rA] = 0.5f * s0;
        g_s[rB] = 0.5f * s1;
    }
}

// ---------------- kernel 2: features (R5 version, 18.9us) --------------------
__device__ __forceinline__ u64 fma2(u64 a, u64 b, u64 c) {
    u64 d;
    asm("fma.rn.f32x2 %0, %1, %2, %3;" : "=l"(d) : "l"(a), "l"(b), "l"(c));
    return d;
}
__device__ __forceinline__ float2 u2f(u64 v) {
    float2 f;
    asm("mov.b64 {%0, %1}, %2;" : "=f"(f.x), "=f"(f.y) : "l"(v));
    return f;
}

__global__ __launch_bounds__(256) void feat_kernel(
    const float* __restrict__ w, float* __restrict__ out)
{
    __shared__ __align__(16) float zs[32][32];
    __shared__ float ss[32];
    const int m  = threadIdx.x;
    const int t0 = blockIdx.x * 32;

    u64 wp[16];
    #pragma unroll
    for (int j = 0; j < 4; j++) {
        ulonglong2 v = *(const ulonglong2*)&w[(size_t)m * DHEAD + j * 8];
        wp[j * 4 + 0] = v.x; wp[j * 4 + 1] = v.y;
        ulonglong2 v2 = *(const ulonglong2*)&w[(size_t)m * DHEAD + j * 8 + 4];
        wp[j * 4 + 2] = v2.x; wp[j * 4 + 3] = v2.y;
    }
    {
        int r = m >> 3, q = m & 7;
        *(float4*)&zs[r][q * 4] = *(const float4*)&g_z[(size_t)(t0 + r) * DHEAD + q * 4];
        if (m < 32) ss[m] = g_s[t0 + m];
    }
    __syncthreads();

    #pragma unroll 4
    for (int tt = 0; tt < 32; tt++) {
        u64 acc0 = 0ull, acc1 = 0ull;
        #pragma unroll
        for (int j = 0; j < 4; j++) {
            ulonglong2 z0 = *(const ulonglong2*)&zs[tt][j * 8];
            ulonglong2 z1 = *(const ulonglong2*)&zs[tt][j * 8 + 4];
            acc0 = fma2(z0.x, wp[j * 4 + 0], acc0);
            acc1 = fma2(z0.y, wp[j * 4 + 1], acc1);
            acc0 = fma2(z1.x, wp[j * 4 + 2], acc0);
            acc1 = fma2(z1.y, wp[j * 4 + 3], acc1);
        }
        float2 f0 = u2f(acc0);
        float2 f1 = u2f(acc1);
        float u = (f0.x + f0.y) + (f1.x + f1.y);
        float s = ss[tt];
        float r = 0.5f * (__expf(u - s) + __expf(-u - s));
        out[(size_t)(t0 + tt) * MFEAT + m] = r;
    }
}

extern "C" void kernel_launch(void* const* d_in, const int* in_sizes, int n_in,
                              void* d_out, int out_size)
{
    const float* x  = (const float*)d_in[0];
    const float* Wq = (const float*)d_in[1];
    const float* bq = (const float*)d_in[2];
    const float* Wk = (const float*)d_in[3];
    const float* bk = (const float*)d_in[4];
    // d_in[5], d_in[6] = Wv, bv: unused (reference discards v)
    const float* w  = (const float*)d_in[7];
    float* out = (float*)d_out;

    wprep_kernel<<<128, 256>>>(Wq, Wk);
    gemm_kernel<<<N_TOK / 128, 256>>>(x, bq, bk);
    feat_kernel<<<N_TOK / 32, 256>>>(w, out);
}

// round 8
// speedup vs baseline: 3.2778x; 1.1703x over previous
#include <cuda_runtime.h>
#include <cuda_bf16.h>
#include <cstdint>

#define N_TOK   16384      // B*T
#define EDIM    1024
#define DHEAD   32
#define MFEAT   256

// ---------------- scratch (__device__ globals; no allocation) ----------------
__device__ float g_z[N_TOK * DHEAD];          // z = q+k (bias incl.)
__device__ float g_s[N_TOK];                  // 0.5*(|q|^2+|k|^2)
// W combined [64 n][1024 k] bf16 hi/lo, per 64-K chunk, 16B-chunk swizzled:
// element (c, n, kk) at [c*4096 + n*64 + ((kk/8 ^ (n&7))*8) + (kk&7)]
__device__ __nv_bfloat16 W_hi_g[16 * 64 * 64];
__device__ __nv_bfloat16 W_lo_g[16 * 64 * 64];

__device__ __forceinline__ uint32_t smem_u32(const void* p) {
    uint32_t a;
    asm("{ .reg .u64 t; cvta.to.shared.u64 t, %1; cvt.u32.u64 %0, t; }" : "=r"(a) : "l"(p));
    return a;
}
__device__ __forceinline__ void ldsm_x4(uint32_t& r0, uint32_t& r1, uint32_t& r2, uint32_t& r3, uint32_t a) {
    asm volatile("ldmatrix.sync.aligned.m8n8.x4.shared.b16 {%0,%1,%2,%3}, [%4];"
                 : "=r"(r0), "=r"(r1), "=r"(r2), "=r"(r3) : "r"(a));
}
__device__ __forceinline__ void ldsm_x2(uint32_t& r0, uint32_t& r1, uint32_t a) {
    asm volatile("ldmatrix.sync.aligned.m8n8.x2.shared.b16 {%0,%1}, [%2];"
                 : "=r"(r0), "=r"(r1) : "r"(a));
}
__device__ __forceinline__ void mma_bf16(float* c, const uint32_t* a, uint32_t b0, uint32_t b1) {
    asm volatile("mma.sync.aligned.m16n8k16.row.col.f32.bf16.bf16.f32 "
                 "{%0,%1,%2,%3}, {%4,%5,%6,%7}, {%8,%9}, {%0,%1,%2,%3};"
                 : "+f"(c[0]), "+f"(c[1]), "+f"(c[2]), "+f"(c[3])
                 : "r"(a[0]), "r"(a[1]), "r"(a[2]), "r"(a[3]), "r"(b0), "r"(b1));
}
__device__ __forceinline__ void cvtpair(float x, float y, uint32_t& h, uint32_t& l) {
    __nv_bfloat162 hh = __float22bfloat162_rn(make_float2(x, y));
    float2 f = __bfloat1622float2(hh);
    __nv_bfloat162 ll = __float22bfloat162_rn(make_float2(x - f.x, y - f.y));
    h = *(uint32_t*)&hh;
    l = *(uint32_t*)&ll;
}

// ---------------- kernel 0: W -> bf16 hi/lo, chunk-swizzled ------------------
__global__ __launch_bounds__(256) void wprep_kernel(
    const float* __restrict__ Wq, const float* __restrict__ Wk)
{
    int idx = blockIdx.x * 256 + threadIdx.x;   // 0..65535
    int c   = idx >> 12;                        // K-chunk 0..15
    int within = idx & 4095;
    int n  = within >> 6;                       // 0..63 (q dims 0-31, k dims 32-63)
    int kk = within & 63;
    int k  = c * 64 + kk;
    float v = (n < 32) ? Wq[(size_t)k * 32 + n] : Wk[(size_t)k * 32 + (n - 32)];
    __nv_bfloat16 h = __float2bfloat16(v);
    __nv_bfloat16 l = __float2bfloat16(v - __bfloat162float(h));
    int pos = c * 4096 + n * 64 + (((kk >> 3) ^ (n & 7)) << 3) + (kk & 7);
    W_hi_g[pos] = h;
    W_lo_g[pos] = l;
}

// ---------------- kernel 1: mma.sync bf16 3-pass projection ------------------
// CTA: 64 rows x 64 cols (q||k). 4 warps, each M=16 x N=64. grid=256.
__global__ __launch_bounds__(128, 2) void gemm_kernel(
    const float* __restrict__ x,
    const float* __restrict__ bq, const float* __restrict__ bk)
{
    __shared__ __align__(16) __nv_bfloat16 Ahi[64 * 64];    // 8KB
    __shared__ __align__(16) __nv_bfloat16 Alo[64 * 64];    // 8KB
    __shared__ __align__(16) __nv_bfloat16 Bhi[64 * 64];    // 8KB
    __shared__ __align__(16) __nv_bfloat16 Blo[64 * 64];    // 8KB

    const int tid = threadIdx.x;
    const int wid = tid >> 5, lid = tid & 31;
    const int row0 = blockIdx.x * 64;

    const uint32_t sAh = smem_u32(Ahi), sAl = smem_u32(Alo);
    const uint32_t sBh = smem_u32(Bhi), sBl = smem_u32(Blo);

    float acc[8][4];
    #pragma unroll
    for (int j = 0; j < 8; j++)
        acc[j][0] = acc[j][1] = acc[j][2] = acc[j][3] = 0.f;

    // staging indices: 512 8-float groups over 128 threads
    int cr[4], ccc[4];
    #pragma unroll
    for (int i = 0; i < 4; i++) {
        int idx = i * 128 + tid;
        cr[i] = idx >> 3;           // row 0..63
        ccc[i] = idx & 7;           // 16B-chunk 0..7
    }
    // ldmatrix lane geometry
    const int i4   = lid >> 3;
    const int arow = wid * 16 + ((i4 & 1) << 3) + (lid & 7);
    const int l7   = lid & 7;
    const int achunk_add = (i4 >> 1);
    const int b_i  = (lid >> 3) & 1;

    // ---- prefetch chunk 0 ----
    float4 xa[4][2];
    uint4 bsh[4], bsl[4];
    #pragma unroll
    for (int i = 0; i < 4; i++) {
        const float4* p = (const float4*)&x[(size_t)(row0 + cr[i]) * EDIM + ccc[i] * 8];
        xa[i][0] = p[0]; xa[i][1] = p[1];
    }
    #pragma unroll
    for (int i = 0; i < 4; i++) {
        int idx = i * 128 + tid;    // 0..511 uint4s
        bsh[i] = ((const uint4*)W_hi_g)[idx];
        bsl[i] = ((const uint4*)W_lo_g)[idx];
    }

    #pragma unroll 1
    for (int c = 0; c < 16; c++) {
        // ---- store staged chunk into smem (swizzled) ----
        #pragma unroll
        for (int i = 0; i < 4; i++) {
            uint4 H, L;
            cvtpair(xa[i][0].x, xa[i][0].y, H.x, L.x);
            cvtpair(xa[i][0].z, xa[i][0].w, H.y, L.y);
            cvtpair(xa[i][1].x, xa[i][1].y, H.z, L.z);
            cvtpair(xa[i][1].z, xa[i][1].w, H.w, L.w);
            uint32_t off = (uint32_t)(cr[i] * 128 + ((ccc[i] ^ (cr[i] & 7)) << 4));
            *(uint4*)((char*)Ahi + off) = H;
            *(uint4*)((char*)Alo + off) = L;
        }
        #pragma unroll
        for (int i = 0; i < 4; i++) {
            int idx = i * 128 + tid;
            ((uint4*)Bhi)[idx] = bsh[i];
            ((uint4*)Blo)[idx] = bsl[i];
        }
        // ---- prefetch chunk c+1 ----
        if (c < 15) {
            #pragma unroll
            for (int i = 0; i < 4; i++) {
                const float4* p = (const float4*)&x[(size_t)(row0 + cr[i]) * EDIM + (c + 1) * 64 + ccc[i] * 8];
                xa[i][0] = p[0]; xa[i][1] = p[1];
            }
            #pragma unroll
            for (int i = 0; i < 4; i++) {
                int idx = i * 128 + tid;
                bsh[i] = ((const uint4*)W_hi_g)[(c + 1) * 512 + idx];
                bsl[i] = ((const uint4*)W_lo_g)[(c + 1) * 512 + idx];
            }
        }
        __syncthreads();
        // ---- MMA phase ----
        #pragma unroll
        for (int gk = 0; gk < 4; gk++) {
            uint32_t ah[4], al[4];
            uint32_t aoff = (uint32_t)(arow * 128 + (((2 * gk + achunk_add) ^ l7) << 4));
            ldsm_x4(ah[0], ah[1], ah[2], ah[3], sAh + aoff);
            ldsm_x4(al[0], al[1], al[2], al[3], sAl + aoff);
            #pragma unroll
            for (int j = 0; j < 8; j++) {
                int brow = 8 * j + l7;
                uint32_t boff = (uint32_t)(brow * 128 + (((2 * gk + b_i) ^ l7) << 4));
                uint32_t bh0, bh1, bl0, bl1;
                ldsm_x2(bh0, bh1, sBh + boff);
                ldsm_x2(bl0, bl1, sBl + boff);
                mma_bf16(acc[j], ah, bh0, bh1);
                mma_bf16(acc[j], ah, bl0, bl1);
                mma_bf16(acc[j], al, bh0, bh1);
            }
        }
        __syncthreads();
    }

    // ---- epilogue: z = q+k (+biases), s = 0.5*sum(q^2+k^2) ----
    const int g = lid >> 2, t = lid & 3;
    const int rA = row0 + wid * 16 + g;
    const int rB = rA + 8;
    float s0 = 0.f, s1 = 0.f;
    #pragma unroll
    for (int j = 0; j < 4; j++) {
        int col = 8 * j + 2 * t;
        float2 bq2 = *(const float2*)&bq[col];
        float2 bk2 = *(const float2*)&bk[col];
        float q00 = acc[j][0] + bq2.x, q01 = acc[j][1] + bq2.y;
        float k00 = acc[j + 4][0] + bk2.x, k01 = acc[j + 4][1] + bk2.y;
        float q10 = acc[j][2] + bq2.x, q11 = acc[j][3] + bq2.y;
        float k10 = acc[j + 4][2] + bk2.x, k11 = acc[j + 4][3] + bk2.y;
        *(float2*)&g_z[(size_t)rA * DHEAD + col] = make_float2(q00 + k00, q01 + k01);
        *(float2*)&g_z[(size_t)rB * DHEAD + col] = make_float2(q10 + k10, q11 + k11);
        s0 += q00 * q00 + q01 * q01 + k00 * k00 + k01 * k01;
        s1 += q10 * q10 + q11 * q11 + k10 * k10 + k11 * k11;
    }
    s0 += __shfl_xor_sync(0xffffffffu, s0, 1);
    s0 += __shfl_xor_sync(0xffffffffu, s0, 2);
    s1 += __shfl_xor_sync(0xffffffffu, s1, 1);
    s1 += __shfl_xor_sync(0xffffffffu, s1, 2);
    if (t == 0) {
        g_s[rA] = 0.5f * s0;
        g_s[rB] = 0.5f * s1;
    }
}

// ---------------- kernel 2: features via mma.sync ----------------------------
// R[t,m] = 0.5*(exp(u-s)+exp(-u-s)), u = z·w_m as bf16 3-pass GEMM.
// CTA: 64 tokens x 256 feats. 8 warps: (wid>>1)=row group of 16, (wid&1)=n-half.
// w in smem, 20-word (80B) padded rows -> conflict-free scalar-LDS B fragments.
__global__ __launch_bounds__(256) void feat_kernel(
    const float* __restrict__ w, float* __restrict__ out)
{
    __shared__ uint32_t wsh[256 * 20];   // 20KB: hi words, [m][kpair], stride 20
    __shared__ uint32_t wsl[256 * 20];   // 20KB: lo words

    const int tid = threadIdx.x;
    const int wid = tid >> 5, lid = tid & 31;
    const int t0  = blockIdx.x * 64;

    // ---- convert w (one row per thread) ----
    {
        const int row = tid;
        #pragma unroll
        for (int j = 0; j < 8; j++) {
            float4 v = *(const float4*)&w[(size_t)row * DHEAD + 4 * j];
            uint32_t h0, l0, h1, l1;
            cvtpair(v.x, v.y, h0, l0);
            cvtpair(v.z, v.w, h1, l1);
            wsh[row * 20 + 2 * j]     = h0;
            wsh[row * 20 + 2 * j + 1] = h1;
            wsl[row * 20 + 2 * j]     = l0;
            wsl[row * 20 + 2 * j + 1] = l1;
        }
    }

    // ---- A fragments from g_z (fp32 -> bf16 hi/lo in-register) ----
    const int g = lid >> 2, t = lid & 3;
    const int r0 = t0 + (wid >> 1) * 16;
    const int nhalf = (wid & 1) * 128;

    uint32_t ah[2][4], al[2][4];
    #pragma unroll
    for (int kg = 0; kg < 2; kg++) {
        #pragma unroll
        for (int h = 0; h < 2; h++) {      // col +0 / +8
            float2 p0 = *(const float2*)&g_z[(size_t)(r0 + g) * DHEAD + kg * 16 + h * 8 + 2 * t];
            float2 p1 = *(const float2*)&g_z[(size_t)(r0 + g + 8) * DHEAD + kg * 16 + h * 8 + 2 * t];
            cvtpair(p0.x, p0.y, ah[kg][2 * h], al[kg][2 * h]);
            cvtpair(p1.x, p1.y, ah[kg][2 * h + 1], al[kg][2 * h + 1]);
        }
    }
    const float s0 = g_s[r0 + g];
    const float s1 = g_s[r0 + g + 8];

    __syncthreads();

    // ---- 16 n-tiles of 8: mma + fused exp epilogue ----
    #pragma unroll 4
    for (int j = 0; j < 16; j++) {
        const int nb = nhalf + 8 * j;
        const uint32_t* bhp = &wsh[(nb + g) * 20 + t];
        const uint32_t* blp = &wsl[(nb + g) * 20 + t];
        uint32_t bh0 = bhp[0], bh1 = bhp[4], bh2 = bhp[8], bh3 = bhp[12];
        uint32_t bl0 = blp[0], bl1 = blp[4], bl2 = blp[8], bl3 = blp[12];

        float c[4] = {0.f, 0.f, 0.f, 0.f};
        mma_bf16(c, ah[0], bh0, bh1);   // hi*hi
        mma_bf16(c, ah[1], bh2, bh3);
        mma_bf16(c, ah[0], bl0, bl1);   // hi*lo
        mma_bf16(c, ah[1], bl2, bl3);
        mma_bf16(c, al[0], bh0, bh1);   // lo*hi
        mma_bf16(c, al[1], bh2, bh3);

        float r00 = 0.5f * (__expf(c[0] - s0) + __expf(-c[0] - s0));
        float r01 = 0.5f * (__expf(c[1] - s0) + __expf(-c[1] - s0));
        float r10 = 0.5f * (__expf(c[2] - s1) + __expf(-c[2] - s1));
        float r11 = 0.5f * (__expf(c[3] - s1) + __expf(-c[3] - s1));
        *(float2*)&out[(size_t)(r0 + g) * MFEAT + nb + 2 * t]     = make_float2(r00, r01);
        *(float2*)&out[(size_t)(r0 + g + 8) * MFEAT + nb + 2 * t] = make_float2(r10, r11);
    }
}

extern "C" void kernel_launch(void* const* d_in, const int* in_sizes, int n_in,
                              void* d_out, int out_size)
{
    const float* x  = (const float*)d_in[0];
    const float* Wq = (const float*)d_in[1];
    const float* bq = (const float*)d_in[2];
    const float* Wk = (const float*)d_in[3];
    const float* bk = (const float*)d_in[4];
    // d_in[5], d_in[6] = Wv, bv: unused (reference discards v)
    const float* w  = (const float*)d_in[7];
    float* out = (float*)d_out;

    wprep_kernel<<<256, 256>>>(Wq, Wk);
    gemm_kernel<<<N_TOK / 64, 128>>>(x, bq, bk);
    feat_kernel<<<N_TOK / 64, 256>>>(w, out);
}

// round 10
// speedup vs baseline: 3.2995x; 1.0066x over previous
#include <cuda_runtime.h>
#include <cuda_bf16.h>
#include <cstdint>

#define N_TOK   16384      // B*T
#define EDIM    1024
#define DHEAD   32
#define MFEAT   256

// ---------------- scratch (__device__ globals; no allocation) ----------------
// W combined [64 n][1024 k] bf16 hi/lo, per 64-K chunk, 16B-chunk swizzled:
// element (c, n, kk) at [c*4096 + n*64 + ((kk/8 ^ (n&7))*8) + (kk&7)]
__device__ __nv_bfloat16 W_hi_g[16 * 64 * 64];
__device__ __nv_bfloat16 W_lo_g[16 * 64 * 64];

__device__ __forceinline__ uint32_t smem_u32(const void* p) {
    uint32_t a;
    asm("{ .reg .u64 t; cvta.to.shared.u64 t, %1; cvt.u32.u64 %0, t; }" : "=r"(a) : "l"(p));
    return a;
}
__device__ __forceinline__ void ldsm_x4(uint32_t& r0, uint32_t& r1, uint32_t& r2, uint32_t& r3, uint32_t a) {
    asm volatile("ldmatrix.sync.aligned.m8n8.x4.shared.b16 {%0,%1,%2,%3}, [%4];"
                 : "=r"(r0), "=r"(r1), "=r"(r2), "=r"(r3) : "r"(a));
}
__device__ __forceinline__ void ldsm_x2(uint32_t& r0, uint32_t& r1, uint32_t a) {
    asm volatile("ldmatrix.sync.aligned.m8n8.x2.shared.b16 {%0,%1}, [%2];"
                 : "=r"(r0), "=r"(r1) : "r"(a));
}
__device__ __forceinline__ void mma_bf16(float* c, const uint32_t* a, uint32_t b0, uint32_t b1) {
    asm volatile("mma.sync.aligned.m16n8k16.row.col.f32.bf16.bf16.f32 "
                 "{%0,%1,%2,%3}, {%4,%5,%6,%7}, {%8,%9}, {%0,%1,%2,%3};"
                 : "+f"(c[0]), "+f"(c[1]), "+f"(c[2]), "+f"(c[3])
                 : "r"(a[0]), "r"(a[1]), "r"(a[2]), "r"(a[3]), "r"(b0), "r"(b1));
}
__device__ __forceinline__ void cvtpair(float x, float y, uint32_t& h, uint32_t& l) {
    __nv_bfloat162 hh = __float22bfloat162_rn(make_float2(x, y));
    float2 f = __bfloat1622float2(hh);
    __nv_bfloat162 ll = __float22bfloat162_rn(make_float2(x - f.x, y - f.y));
    h = *(uint32_t*)&hh;
    l = *(uint32_t*)&ll;
}

// ---------------- kernel 0: W -> bf16 hi/lo, chunk-swizzled, coalesced reads -
__global__ __launch_bounds__(256) void wprep_kernel(
    const float* __restrict__ Wq, const float* __restrict__ Wk)
{
    int idx = blockIdx.x * 256 + threadIdx.x;   // 0..65535
    int c   = idx >> 12;                        // K-chunk 0..15
    int kk  = (idx >> 6) & 63;
    int n   = idx & 63;                         // consecutive threads -> consecutive n (coalesced)
    int k   = c * 64 + kk;
    float v = (n < 32) ? Wq[(size_t)k * 32 + n] : Wk[(size_t)k * 32 + (n - 32)];
    __nv_bfloat16 h = __float2bfloat16(v);
    __nv_bfloat16 l = __float2bfloat16(v - __bfloat162float(h));
    int pos = c * 4096 + n * 64 + (((kk >> 3) ^ (n & 7)) << 3) + (kk & 7);
    W_hi_g[pos] = h;
    W_lo_g[pos] = l;
}

// ---------------- fused kernel: projection GEMM + features ------------------
// CTA: 64 tokens. Phase 1: z,s via bf16 3-pass mma over K=1024 (as R8 gemm).
// Phase 2: z-accumulator fragments ARE the feat A-fragments (cols = feat K dim);
// convert in-register, then 32 n-tiles of 8 feats with fused exp epilogue.
#define SM_A_HI   0
#define SM_A_LO   8192
#define SM_B_HI   16384
#define SM_B_LO   24576
#define SM_WSH    32768                 // uint32[256*20] = 20480 B
#define SM_WSL    53248
#define SMEM_SZ   73728

__global__ __launch_bounds__(128, 2) void fused_kernel(
    const float* __restrict__ x,
    const float* __restrict__ bq, const float* __restrict__ bk,
    const float* __restrict__ w, float* __restrict__ out)
{
    extern __shared__ __align__(16) char sm[];
    char* Ahi = sm + SM_A_HI;
    char* Alo = sm + SM_A_LO;
    char* Bhi = sm + SM_B_HI;
    char* Blo = sm + SM_B_LO;
    uint32_t* wsh = (uint32_t*)(sm + SM_WSH);
    uint32_t* wsl = (uint32_t*)(sm + SM_WSL);

    const int tid = threadIdx.x;
    const int wid = tid >> 5, lid = tid & 31;
    const int row0 = blockIdx.x * 64;

    const uint32_t sAh = smem_u32(Ahi), sAl = smem_u32(Alo);
    const uint32_t sBh = smem_u32(Bhi), sBl = smem_u32(Blo);

    float acc[8][4];
    #pragma unroll
    for (int j = 0; j < 8; j++)
        acc[j][0] = acc[j][1] = acc[j][2] = acc[j][3] = 0.f;

    // staging indices: 512 8-float groups over 128 threads
    int cr[4], ccc[4];
    #pragma unroll
    for (int i = 0; i < 4; i++) {
        int idx = i * 128 + tid;
        cr[i] = idx >> 3;
        ccc[i] = idx & 7;
    }
    // ldmatrix lane geometry
    const int i4   = lid >> 3;
    const int arow = wid * 16 + ((i4 & 1) << 3) + (lid & 7);
    const int l7   = lid & 7;
    const int achunk_add = (i4 >> 1);
    const int b_i  = (lid >> 3) & 1;

    // ---- prefetch chunk 0 (critical path) ----
    float4 xa[4][2];
    uint4 bsh[4], bsl[4];
    #pragma unroll
    for (int i = 0; i < 4; i++) {
        const float4* p = (const float4*)&x[(size_t)(row0 + cr[i]) * EDIM + ccc[i] * 8];
        xa[i][0] = p[0]; xa[i][1] = p[1];
    }
    #pragma unroll
    for (int i = 0; i < 4; i++) {
        int idx = i * 128 + tid;
        bsh[i] = ((const uint4*)W_hi_g)[idx];
        bsl[i] = ((const uint4*)W_lo_g)[idx];
    }

    // ---- convert w into smem (2 rows per thread); visible after first sync --
    #pragma unroll
    for (int rr = 0; rr < 2; rr++) {
        const int row = tid + rr * 128;
        #pragma unroll
        for (int j = 0; j < 8; j++) {
            float4 v = *(const float4*)&w[(size_t)row * DHEAD + 4 * j];
            uint32_t h0, l0, h1, l1;
            cvtpair(v.x, v.y, h0, l0);
            cvtpair(v.z, v.w, h1, l1);
            wsh[row * 20 + 2 * j]     = h0;
            wsh[row * 20 + 2 * j + 1] = h1;
            wsl[row * 20 + 2 * j]     = l0;
            wsl[row * 20 + 2 * j + 1] = l1;
        }
    }

    // ================= phase 1: projection mainloop =================
    #pragma unroll 1
    for (int c = 0; c < 16; c++) {
        #pragma unroll
        for (int i = 0; i < 4; i++) {
            uint4 H, L;
            cvtpair(xa[i][0].x, xa[i][0].y, H.x, L.x);
            cvtpair(xa[i][0].z, xa[i][0].w, H.y, L.y);
            cvtpair(xa[i][1].x, xa[i][1].y, H.z, L.z);
            cvtpair(xa[i][1].z, xa[i][1].w, H.w, L.w);
            uint32_t off = (uint32_t)(cr[i] * 128 + ((ccc[i] ^ (cr[i] & 7)) << 4));
            *(uint4*)(Ahi + off) = H;
            *(uint4*)(Alo + off) = L;
        }
        #pragma unroll
        for (int i = 0; i < 4; i++) {
            int idx = i * 128 + tid;
            ((uint4*)Bhi)[idx] = bsh[i];
            ((uint4*)Blo)[idx] = bsl[i];
        }
        if (c < 15) {
            #pragma unroll
            for (int i = 0; i < 4; i++) {
                const float4* p = (const float4*)&x[(size_t)(row0 + cr[i]) * EDIM + (c + 1) * 64 + ccc[i] * 8];
                xa[i][0] = p[0]; xa[i][1] = p[1];
            }
            #pragma unroll
            for (int i = 0; i < 4; i++) {
                int idx = i * 128 + tid;
                bsh[i] = ((const uint4*)W_hi_g)[(c + 1) * 512 + idx];
                bsl[i] = ((const uint4*)W_lo_g)[(c + 1) * 512 + idx];
            }
        }
        __syncthreads();
        #pragma unroll
        for (int gk = 0; gk < 4; gk++) {
            uint32_t ah4[4], al4[4];
            uint32_t aoff = (uint32_t)(arow * 128 + (((2 * gk + achunk_add) ^ l7) << 4));
            ldsm_x4(ah4[0], ah4[1], ah4[2], ah4[3], sAh + aoff);
            ldsm_x4(al4[0], al4[1], al4[2], al4[3], sAl + aoff);
            #pragma unroll
            for (int j = 0; j < 8; j++) {
                int brow = 8 * j + l7;
                uint32_t boff = (uint32_t)(brow * 128 + (((2 * gk + b_i) ^ l7) << 4));
                uint32_t bh0, bh1, bl0, bl1;
                ldsm_x2(bh0, bh1, sBh + boff);
                ldsm_x2(bl0, bl1, sBl + boff);
                mma_bf16(acc[j], ah4, bh0, bh1);
                mma_bf16(acc[j], ah4, bl0, bl1);
                mma_bf16(acc[j], al4, bh0, bh1);
            }
        }
        __syncthreads();
    }

    // ============ phase 2: z frags in-register + s, then features ============
    const int g = lid >> 2, t = lid & 3;
    const int r0 = row0 + wid * 16 + g;       // token row (and r0+8)

    uint32_t ah[2][4], al[2][4];
    float s0 = 0.f, s1 = 0.f;
    #pragma unroll
    for (int kg = 0; kg < 2; kg++) {
        #pragma unroll
        for (int h = 0; h < 2; h++) {
            const int j = 2 * kg + h;         // q acc index; k acc is j+4
            const int col = 8 * j + 2 * t;
            float2 bq2 = *(const float2*)&bq[col];
            float2 bk2 = *(const float2*)&bk[col];
            float q00 = acc[j][0] + bq2.x, q01 = acc[j][1] + bq2.y;       // row g
            float k00 = acc[j + 4][0] + bk2.x, k01 = acc[j + 4][1] + bk2.y;
            float q10 = acc[j][2] + bq2.x, q11 = acc[j][3] + bq2.y;       // row g+8
            float k10 = acc[j + 4][2] + bk2.x, k11 = acc[j + 4][3] + bk2.y;
            s0 += q00 * q00 + q01 * q01 + k00 * k00 + k01 * k01;
            s1 += q10 * q10 + q11 * q11 + k10 * k10 + k11 * k11;
            cvtpair(q00 + k00, q01 + k01, ah[kg][2 * h],     al[kg][2 * h]);
            cvtpair(q10 + k10, q11 + k11, ah[kg][2 * h + 1], al[kg][2 * h + 1]);
        }
    }
    s0 += __shfl_xor_sync(0xffffffffu, s0, 1);
    s0 += __shfl_xor_sync(0xffffffffu, s0, 2);
    s1 += __shfl_xor_sync(0xffffffffu, s1, 1);
    s1 += __shfl_xor_sync(0xffffffffu, s1, 2);
    s0 *= 0.5f;
    s1 *= 0.5f;

    // feat: 32 n-tiles of 8 over all 256 feats (w smem synced in mainloop)
    #pragma unroll 4
    for (int j = 0; j < 32; j++) {
        const int nb = 8 * j;
        const uint32_t* bhp = &wsh[(nb + g) * 20 + t];
        const uint32_t* blp = &wsl[(nb + g) * 20 + t];
        uint32_t bh0 = bhp[0], bh1 = bhp[4], bh2 = bhp[8], bh3 = bhp[12];
        uint32_t bl0 = blp[0], bl1 = blp[4], bl2 = blp[8], bl3 = blp[12];

        float c[4] = {0.f, 0.f, 0.f, 0.f};
        mma_bf16(c, ah[0], bh0, bh1);   // hi*hi
        mma_bf16(c, ah[1], bh2, bh3);
        mma_bf16(c, ah[0], bl0, bl1);   // hi*lo
        mma_bf16(c, ah[1], bl2, bl3);
        mma_bf16(c, al[0], bh0, bh1);   // lo*hi
        mma_bf16(c, al[1], bh2, bh3);

        float r00 = 0.5f * (__expf(c[0] - s0) + __expf(-c[0] - s0));
        float r01 = 0.5f * (__expf(c[1] - s0) + __expf(-c[1] - s0));
        float r10 = 0.5f * (__expf(c[2] - s1) + __expf(-c[2] - s1));
        float r11 = 0.5f * (__expf(c[3] - s1) + __expf(-c[3] - s1));
        *(float2*)&out[(size_t)r0 * MFEAT + nb + 2 * t]       = make_float2(r00, r01);
        *(float2*)&out[(size_t)(r0 + 8) * MFEAT + nb + 2 * t] = make_float2(r10, r11);
    }
}

extern "C" void kernel_launch(void* const* d_in, const int* in_sizes, int n_in,
                              void* d_out, int out_size)
{
    const float* x  = (const float*)d_in[0];
    const float* Wq = (const float*)d_in[1];
    const float* bq = (const float*)d_in[2];
    const float* Wk = (const float*)d_in[3];
    const float* bk = (const float*)d_in[4];
    // d_in[5], d_in[6] = Wv, bv: unused (reference discards v)
    const float* w  = (const float*)d_in[7];
    float* out = (float*)d_out;

    static bool attr_set = false;   // idempotent host-side attribute
    if (!attr_set) {
        cudaFuncSetAttribute(fused_kernel, cudaFuncAttributeMaxDynamicSharedMemorySize, SMEM_SZ);
        attr_set = true;
    }
    wprep_kernel<<<256, 256>>>(Wq, Wk);
    fused_kernel<<<N_TOK / 64, 128, SMEM_SZ>>>(x, bq, bk, w, out);
}

// round 11
// speedup vs baseline: 3.4387x; 1.0422x over previous
#include <cuda_runtime.h>
#include <cuda_bf16.h>
#include <cstdint>

#define N_TOK   16384      // B*T
#define EDIM    1024
#define DHEAD   32
#define MFEAT   256

// ---------------- scratch (__device__ globals; no allocation) ----------------
// W combined [64 n][1024 k] bf16 hi/lo, per 64-K chunk, 16B-chunk swizzled:
// element (c, n, kk) at [c*4096 + n*64 + ((kk/8 ^ (n&7))*8) + (kk&7)]
__device__ __nv_bfloat16 W_hi_g[16 * 64 * 64];
__device__ __nv_bfloat16 W_lo_g[16 * 64 * 64];

__device__ __forceinline__ uint32_t smem_u32(const void* p) {
    uint32_t a;
    asm("{ .reg .u64 t; cvta.to.shared.u64 t, %1; cvt.u32.u64 %0, t; }" : "=r"(a) : "l"(p));
    return a;
}
__device__ __forceinline__ void ldsm_x4(uint32_t& r0, uint32_t& r1, uint32_t& r2, uint32_t& r3, uint32_t a) {
    asm volatile("ldmatrix.sync.aligned.m8n8.x4.shared.b16 {%0,%1,%2,%3}, [%4];"
                 : "=r"(r0), "=r"(r1), "=r"(r2), "=r"(r3) : "r"(a));
}
__device__ __forceinline__ void ldsm_x2(uint32_t& r0, uint32_t& r1, uint32_t a) {
    asm volatile("ldmatrix.sync.aligned.m8n8.x2.shared.b16 {%0,%1}, [%2];"
                 : "=r"(r0), "=r"(r1) : "r"(a));
}
__device__ __forceinline__ void mma_bf16(float* c, const uint32_t* a, uint32_t b0, uint32_t b1) {
    asm volatile("mma.sync.aligned.m16n8k16.row.col.f32.bf16.bf16.f32 "
                 "{%0,%1,%2,%3}, {%4,%5,%6,%7}, {%8,%9}, {%0,%1,%2,%3};"
                 : "+f"(c[0]), "+f"(c[1]), "+f"(c[2]), "+f"(c[3])
                 : "r"(a[0]), "r"(a[1]), "r"(a[2]), "r"(a[3]), "r"(b0), "r"(b1));
}
__device__ __forceinline__ void cvtpair(float x, float y, uint32_t& h, uint32_t& l) {
    __nv_bfloat162 hh = __float22bfloat162_rn(make_float2(x, y));
    float2 f = __bfloat1622float2(hh);
    __nv_bfloat162 ll = __float22bfloat162_rn(make_float2(x - f.x, y - f.y));
    h = *(uint32_t*)&hh;
    l = *(uint32_t*)&ll;
}
__device__ __forceinline__ void cp_async16(uint32_t dst, const void* src) {
    asm volatile("cp.async.cg.shared.global [%0], [%1], 16;" :: "r"(dst), "l"(src) : "memory");
}
#define CP_COMMIT()  asm volatile("cp.async.commit_group;" ::: "memory")
#define CP_WAIT(n)   asm volatile("cp.async.wait_group %0;" :: "n"(n) : "memory")

// ---------------- kernel 0: W -> bf16 hi/lo, chunk-swizzled ------------------
__global__ __launch_bounds__(256) void wprep_kernel(
    const float* __restrict__ Wq, const float* __restrict__ Wk)
{
    int idx  = blockIdx.x * 256 + threadIdx.x;   // 0..16383
    int c    = idx >> 10;
    int rest = idx & 1023;
    int kk   = rest >> 4;
    int ng   = rest & 15;                        // group of 4 n
    int k    = c * 64 + kk;
    float4 v = (ng < 8) ? ((const float4*)Wq)[k * 8 + ng]
                        : ((const float4*)Wk)[k * 8 + (ng - 8)];
    const float* vp = &v.x;
    #pragma unroll
    for (int e = 0; e < 4; e++) {
        int n = ng * 4 + e;
        float f = vp[e];
        __nv_bfloat16 h = __float2bfloat16(f);
        __nv_bfloat16 l = __float2bfloat16(f - __bfloat162float(h));
        int pos = c * 4096 + n * 64 + (((kk >> 3) ^ (n & 7)) << 3) + (kk & 7);
        W_hi_g[pos] = h;
        W_lo_g[pos] = l;
    }
}

// ---------------- fused kernel: projection GEMM + features ------------------
// 256 thr / 8 warps, M=64 tokens/CTA, grid 256.
// Phase 1: warp (wid>>1 = row group of 16, wid&1 = h) computes q/k dims
//          16h..16h+15 via bf16 3-pass mma; B tiles arrive by cp.async.
// Exchange: q,k (+bias) -> zq/zk smem (aliased over A); rebuild feat A-frags + s.
// Phase 2: feat n-half (wid&1)*128, 16 n-tiles of 8, fused exp epilogue.
#define SM_AHI    0              // 8KB  (phase2: zq 64x32 f32)
#define SM_ALO    8192           // 8KB  (phase2: zk)
#define SM_B      16384          // 2 bufs x (hi 8KB + lo 8KB) = 32KB
#define SM_WSH    16384          // phase2 alias: uint32[256*20]
#define SM_WSL    36864
#define SMEM_SZ   57344

__global__ __launch_bounds__(256, 2) void fused_kernel(
    const float* __restrict__ x,
    const float* __restrict__ bq, const float* __restrict__ bk,
    const float* __restrict__ w, float* __restrict__ out)
{
    extern __shared__ __align__(16) char sm[];
    char* Ahi = sm + SM_AHI;
    char* Alo = sm + SM_ALO;
    float* zq = (float*)(sm + SM_AHI);
    float* zk = (float*)(sm + SM_ALO);
    uint32_t* wsh = (uint32_t*)(sm + SM_WSH);
    uint32_t* wsl = (uint32_t*)(sm + SM_WSL);

    const int tid = threadIdx.x;
    const int wid = tid >> 5, lid = tid & 31;
    const int row0 = blockIdx.x * 64;

    const uint32_t sAh = smem_u32(Ahi), sAl = smem_u32(Alo);
    const uint32_t sB  = smem_u32(sm + SM_B);

    const int mwrow = (wid >> 1) * 16;    // warp's row group (CTA-local)
    const int h     = wid & 1;            // dim-half

    float acc[4][4];                       // tiles: q{2h,2h+1}, k{4+2h,5+2h}
    #pragma unroll
    for (int j = 0; j < 4; j++)
        acc[j][0] = acc[j][1] = acc[j][2] = acc[j][3] = 0.f;

    // x staging indices: 512 8-float groups over 256 threads
    int cr[2], cc8[2];
    #pragma unroll
    for (int i = 0; i < 2; i++) {
        int idx = i * 256 + tid;
        cr[i]  = idx >> 3;
        cc8[i] = idx & 7;
    }
    // ldmatrix lane geometry
    const int i4   = lid >> 3;
    const int arow = mwrow + ((i4 & 1) << 3) + (lid & 7);
    const int l7   = lid & 7;
    const int achunk_add = (i4 >> 1);
    const int b_i  = (lid >> 3) & 1;

    // ---- preload: cp.async B chunk 0 into buf 0; stage x chunk 0 ----
    #pragma unroll
    for (int i = 0; i < 2; i++) {
        int u = i * 256 + tid;            // 0..511 16B units
        cp_async16(sB + u * 16,        (const char*)W_hi_g + u * 16);
        cp_async16(sB + 8192 + u * 16, (const char*)W_lo_g + u * 16);
    }
    CP_COMMIT();

    float4 xa[2][2];
    #pragma unroll
    for (int i = 0; i < 2; i++) {
        const float4* p = (const float4*)&x[(size_t)(row0 + cr[i]) * EDIM + cc8[i] * 8];
        xa[i][0] = p[0]; xa[i][1] = p[1];
    }

    // ================= phase 1: projection mainloop =================
    #pragma unroll 1
    for (int c = 0; c < 16; c++) {
        const int buf = c & 1;
        // store staged x chunk into A smem (swizzled bf16 hi/lo)
        #pragma unroll
        for (int i = 0; i < 2; i++) {
            uint4 H, L;
            cvtpair(xa[i][0].x, xa[i][0].y, H.x, L.x);
            cvtpair(xa[i][0].z, xa[i][0].w, H.y, L.y);
            cvtpair(xa[i][1].x, xa[i][1].y, H.z, L.z);
            cvtpair(xa[i][1].z, xa[i][1].w, H.w, L.w);
            uint32_t off = (uint32_t)(cr[i] * 128 + ((cc8[i] ^ (cr[i] & 7)) << 4));
            *(uint4*)(Ahi + off) = H;
            *(uint4*)(Alo + off) = L;
        }
        if (c < 15) {
            // prefetch x chunk c+1 into regs
            #pragma unroll
            for (int i = 0; i < 2; i++) {
                const float4* p = (const float4*)&x[(size_t)(row0 + cr[i]) * EDIM + (c + 1) * 64 + cc8[i] * 8];
                xa[i][0] = p[0]; xa[i][1] = p[1];
            }
            // cp.async B chunk c+1 into other buf
            const uint32_t db = sB + (buf ^ 1) * 16384;
            const size_t gb = (size_t)(c + 1) * 8192;
            #pragma unroll
            for (int i = 0; i < 2; i++) {
                int u = i * 256 + tid;
                cp_async16(db + u * 16,        (const char*)W_hi_g + gb + u * 16);
                cp_async16(db + 8192 + u * 16, (const char*)W_lo_g + gb + u * 16);
            }
            CP_COMMIT();
            CP_WAIT(1);
        } else {
            CP_WAIT(0);
        }
        __syncthreads();
        // MMA phase: 4 k16-groups x 4 n-tiles x 3 passes
        const uint32_t sBh = sB + buf * 16384;
        const uint32_t sBl = sBh + 8192;
        #pragma unroll
        for (int gk = 0; gk < 4; gk++) {
            uint32_t ah4[4], al4[4];
            uint32_t aoff = (uint32_t)(arow * 128 + (((2 * gk + achunk_add) ^ l7) << 4));
            ldsm_x4(ah4[0], ah4[1], ah4[2], ah4[3], sAh + aoff);
            ldsm_x4(al4[0], al4[1], al4[2], al4[3], sAl + aoff);
            #pragma unroll
            for (int jj = 0; jj < 4; jj++) {
                const int j = (jj < 2) ? (2 * h + jj) : (2 + 2 * h + jj);   // n-tile
                int brow = 8 * j + l7;
                uint32_t boff = (uint32_t)(brow * 128 + (((2 * gk + b_i) ^ l7) << 4));
                uint32_t bh0, bh1, bl0, bl1;
                ldsm_x2(bh0, bh1, sBh + boff);
                ldsm_x2(bl0, bl1, sBl + boff);
                mma_bf16(acc[jj], ah4, bh0, bh1);
                mma_bf16(acc[jj], ah4, bl0, bl1);
                mma_bf16(acc[jj], al4, bh0, bh1);
            }
        }
        __syncthreads();
    }

    // ============ exchange: q,k (+bias) -> zq/zk smem (alias A) ============
    const int g = lid >> 2, t = lid & 3;
    {
        const int lr0 = mwrow + g, lr1 = lr0 + 8;
        #pragma unroll
        for (int jj = 0; jj < 2; jj++) {          // q tiles
            int col = 16 * h + 8 * jj + 2 * t;
            float2 b2 = *(const float2*)&bq[col];
            *(float2*)&zq[lr0 * 32 + col] = make_float2(acc[jj][0] + b2.x, acc[jj][1] + b2.y);
            *(float2*)&zq[lr1 * 32 + col] = make_float2(acc[jj][2] + b2.x, acc[jj][3] + b2.y);
        }
        #pragma unroll
        for (int jj = 2; jj < 4; jj++) {          // k tiles
            int col = 16 * h + 8 * (jj - 2) + 2 * t;
            float2 b2 = *(const float2*)&bk[col];
            *(float2*)&zk[lr0 * 32 + col] = make_float2(acc[jj][0] + b2.x, acc[jj][1] + b2.y);
            *(float2*)&zk[lr1 * 32 + col] = make_float2(acc[jj][2] + b2.x, acc[jj][3] + b2.y);
        }
    }
    // convert w into smem (1 row per thread) — region independent of zq/zk
    {
        const int row = tid;
        #pragma unroll
        for (int j = 0; j < 8; j++) {
            float4 v = *(const float4*)&w[(size_t)row * DHEAD + 4 * j];
            uint32_t h0, l0, h1, l1;
            cvtpair(v.x, v.y, h0, l0);
            cvtpair(v.z, v.w, h1, l1);
            wsh[row * 20 + 2 * j]     = h0;
            wsh[row * 20 + 2 * j + 1] = h1;
            wsl[row * 20 + 2 * j]     = l0;
            wsl[row * 20 + 2 * j + 1] = l1;
        }
    }
    __syncthreads();

    // ============ rebuild feat A-frags + s from zq/zk ============
    const int lr0 = mwrow + g, lr1 = lr0 + 8;
    uint32_t ah[2][4], al[2][4];
    float s0 = 0.f, s1 = 0.f;
    #pragma unroll
    for (int kg = 0; kg < 2; kg++) {
        #pragma unroll
        for (int hh = 0; hh < 2; hh++) {
            int col = kg * 16 + hh * 8 + 2 * t;
            float2 q0 = *(const float2*)&zq[lr0 * 32 + col];
            float2 k0 = *(const float2*)&zk[lr0 * 32 + col];
            float2 q1 = *(const float2*)&zq[lr1 * 32 + col];
            float2 k1 = *(const float2*)&zk[lr1 * 32 + col];
            s0 += q0.x * q0.x + q0.y * q0.y + k0.x * k0.x + k0.y * k0.y;
            s1 += q1.x * q1.x + q1.y * q1.y + k1.x * k1.x + k1.y * k1.y;
            cvtpair(q0.x + k0.x, q0.y + k0.y, ah[kg][2 * hh],     al[kg][2 * hh]);
            cvtpair(q1.x + k1.x, q1.y + k1.y, ah[kg][2 * hh + 1], al[kg][2 * hh + 1]);
        }
    }
    s0 += __shfl_xor_sync(0xffffffffu, s0, 1);
    s0 += __shfl_xor_sync(0xffffffffu, s0, 2);
    s1 += __shfl_xor_sync(0xffffffffu, s1, 1);
    s1 += __shfl_xor_sync(0xffffffffu, s1, 2);
    s0 *= 0.5f;
    s1 *= 0.5f;

    // ============ phase 2: features (n-half per warp) ============
    const int r0 = row0 + lr0;
    const int nhalf = h * 128;
    #pragma unroll 4
    for (int j = 0; j < 16; j++) {
        const int nb = nhalf + 8 * j;
        const uint32_t* bhp = &wsh[(nb + g) * 20 + t];
        const uint32_t* blp = &wsl[(nb + g) * 20 + t];
        uint32_t bh0 = bhp[0], bh1 = bhp[4], bh2 = bhp[8], bh3 = bhp[12];
        uint32_t bl0 = blp[0], bl1 = blp[4], bl2 = blp[8], bl3 = blp[12];

        float c[4] = {0.f, 0.f, 0.f, 0.f};
        mma_bf16(c, ah[0], bh0, bh1);   // hi*hi
        mma_bf16(c, ah[1], bh2, bh3);
        mma_bf16(c, ah[0], bl0, bl1);   // hi*lo
        mma_bf16(c, ah[1], bl2, bl3);
        mma_bf16(c, al[0], bh0, bh1);   // lo*hi
        mma_bf16(c, al[1], bh2, bh3);

        float r00 = 0.5f * (__expf(c[0] - s0) + __expf(-c[0] - s0));
        float r01 = 0.5f * (__expf(c[1] - s0) + __expf(-c[1] - s0));
        float r10 = 0.5f * (__expf(c[2] - s1) + __expf(-c[2] - s1));
        float r11 = 0.5f * (__expf(c[3] - s1) + __expf(-c[3] - s1));
        *(float2*)&out[(size_t)r0 * MFEAT + nb + 2 * t]       = make_float2(r00, r01);
        *(float2*)&out[(size_t)(r0 + 8) * MFEAT + nb + 2 * t] = make_float2(r10, r11);
    }
}

extern "C" void kernel_launch(void* const* d_in, const int* in_sizes, int n_in,
                              void* d_out, int out_size)
{
    const float* x  = (const float*)d_in[0];
    const float* Wq = (const float*)d_in[1];
    const float* bq = (const float*)d_in[2];
    const float* Wk = (const float*)d_in[3];
    const float* bk = (const float*)d_in[4];
    // d_in[5], d_in[6] = Wv, bv: unused (reference discards v)
    const float* w  = (const float*)d_in[7];
    float* out = (float*)d_out;

    static bool attr_set = false;   // idempotent host-side attribute
    if (!attr_set) {
        cudaFuncSetAttribute(fused_kernel, cudaFuncAttributeMaxDynamicSharedMemorySize, SMEM_SZ);
        attr_set = true;
    }
    wprep_kernel<<<64, 256>>>(Wq, Wk);
    fused_kernel<<<N_TOK / 64, 256, SMEM_SZ>>>(x, bq, bk, w, out);
}

// round 12
// speedup vs baseline: 3.4599x; 1.0062x over previous
#include <cuda_runtime.h>
#include <cuda_bf16.h>
#include <cstdint>

#define N_TOK   16384      // B*T
#define EDIM    1024
#define DHEAD   32
#define MFEAT   256

// ---------------- scratch (__device__ globals; no allocation) ----------------
// W combined [64 n][1024 k] bf16 hi/lo, per 64-K chunk, 16B-chunk swizzled:
// element (c, n, kk) at [c*4096 + n*64 + ((kk/8 ^ (n&7))*8) + (kk&7)]
__device__ __nv_bfloat16 W_hi_g[16 * 64 * 64];
__device__ __nv_bfloat16 W_lo_g[16 * 64 * 64];

__device__ __forceinline__ uint32_t smem_u32(const void* p) {
    uint32_t a;
    asm("{ .reg .u64 t; cvta.to.shared.u64 t, %1; cvt.u32.u64 %0, t; }" : "=r"(a) : "l"(p));
    return a;
}
__device__ __forceinline__ void ldsm_x4(uint32_t& r0, uint32_t& r1, uint32_t& r2, uint32_t& r3, uint32_t a) {
    asm volatile("ldmatrix.sync.aligned.m8n8.x4.shared.b16 {%0,%1,%2,%3}, [%4];"
                 : "=r"(r0), "=r"(r1), "=r"(r2), "=r"(r3) : "r"(a));
}
__device__ __forceinline__ void mma_bf16(float* c, const uint32_t* a, uint32_t b0, uint32_t b1) {
    asm volatile("mma.sync.aligned.m16n8k16.row.col.f32.bf16.bf16.f32 "
                 "{%0,%1,%2,%3}, {%4,%5,%6,%7}, {%8,%9}, {%0,%1,%2,%3};"
                 : "+f"(c[0]), "+f"(c[1]), "+f"(c[2]), "+f"(c[3])
                 : "r"(a[0]), "r"(a[1]), "r"(a[2]), "r"(a[3]), "r"(b0), "r"(b1));
}
__device__ __forceinline__ void cvtpair(float x, float y, uint32_t& h, uint32_t& l) {
    __nv_bfloat162 hh = __float22bfloat162_rn(make_float2(x, y));
    float2 f = __bfloat1622float2(hh);
    __nv_bfloat162 ll = __float22bfloat162_rn(make_float2(x - f.x, y - f.y));
    h = *(uint32_t*)&hh;
    l = *(uint32_t*)&ll;
}
__device__ __forceinline__ void cp_async16(uint32_t dst, const void* src) {
    asm volatile("cp.async.cg.shared.global [%0], [%1], 16;" :: "r"(dst), "l"(src) : "memory");
}
#define CP_COMMIT()  asm volatile("cp.async.commit_group;" ::: "memory")
#define CP_WAIT(n)   asm volatile("cp.async.wait_group %0;" :: "n"(n) : "memory")

// ---------------- kernel 0: W -> bf16 hi/lo, chunk-swizzled ------------------
__global__ __launch_bounds__(256) void wprep_kernel(
    const float* __restrict__ Wq, const float* __restrict__ Wk)
{
    int idx  = blockIdx.x * 256 + threadIdx.x;   // 0..16383
    int c    = idx >> 10;
    int rest = idx & 1023;
    int kk   = rest >> 4;
    int ng   = rest & 15;                        // group of 4 n
    int k    = c * 64 + kk;
    float4 v = (ng < 8) ? ((const float4*)Wq)[k * 8 + ng]
                        : ((const float4*)Wk)[k * 8 + (ng - 8)];
    const float* vp = &v.x;
    #pragma unroll
    for (int e = 0; e < 4; e++) {
        int n = ng * 4 + e;
        float f = vp[e];
        __nv_bfloat16 h = __float2bfloat16(f);
        __nv_bfloat16 l = __float2bfloat16(f - __bfloat162float(h));
        int pos = c * 4096 + n * 64 + (((kk >> 3) ^ (n & 7)) << 3) + (kk & 7);
        W_hi_g[pos] = h;
        W_lo_g[pos] = l;
    }
}

// ---------------- fused kernel: projection GEMM + features ------------------
// 256 thr / 8 warps, M=64 tokens/CTA, grid 256.
// Pipeline: A double-buffered (stage c+1 during MMA of c), B triple-buffered
// cp.async with 2-chunk lookahead, x LDG 2-chunk prefetch, ONE sync per chunk.
// Phase 2 aliases: zq/zk over A, w-tables over B.
#define SM_A      0              // 2 bufs x (hi 8K + lo 8K) = 32KB
#define SM_B      32768          // 3 bufs x (hi 8K + lo 8K) = 48KB
#define SM_WSH    32768          // phase2 alias over B: uint32[256*20]
#define SM_WSL    53248
#define SMEM_SZ   81920

__global__ __launch_bounds__(256, 2) void fused_kernel(
    const float* __restrict__ x,
    const float* __restrict__ bq, const float* __restrict__ bk,
    const float* __restrict__ w, float* __restrict__ out)
{
    extern __shared__ __align__(16) char sm[];
    float* zq = (float*)(sm + SM_A);            // phase2 alias (A dead)
    float* zk = (float*)(sm + SM_A + 8192);
    uint32_t* wsh = (uint32_t*)(sm + SM_WSH);   // phase2 alias (B dead)
    uint32_t* wsl = (uint32_t*)(sm + SM_WSL);

    const int tid = threadIdx.x;
    const int wid = tid >> 5, lid = tid & 31;
    const int row0 = blockIdx.x * 64;

    const uint32_t smb = smem_u32(sm);
    const uint32_t sA = smb + SM_A;
    const uint32_t sB = smb + SM_B;

    const int mwrow = (wid >> 1) * 16;    // warp's row group (CTA-local)
    const int h     = wid & 1;            // dim-half

    float acc[4][4];                       // tiles: q{2h,2h+1}, k{4+2h,5+2h}
    #pragma unroll
    for (int j = 0; j < 4; j++)
        acc[j][0] = acc[j][1] = acc[j][2] = acc[j][3] = 0.f;

    // x staging indices: 512 8-float groups over 256 threads
    int cr[2], cc8[2];
    #pragma unroll
    for (int i = 0; i < 2; i++) {
        int idx = i * 256 + tid;
        cr[i]  = idx >> 3;
        cc8[i] = idx & 7;
    }
    // ldmatrix lane geometry (x4 for both A and B)
    const int i4   = lid >> 3;
    const int arow = mwrow + ((i4 & 1) << 3) + (lid & 7);
    const int l7   = lid & 7;
    const int achunk_add = i4 >> 1;       // A: k-chunk half
    const int bt_add     = i4 >> 1;       // B: tile within pair
    const int bk_half    = i4 & 1;        // B: k half

    // ---- prologue: cp.async B0, B1 ----
    #pragma unroll
    for (int cc = 0; cc < 2; cc++) {
        uint32_t db = sB + cc * 16384;
        size_t gb = (size_t)cc * 8192;
        #pragma unroll
        for (int i = 0; i < 2; i++) {
            int u = i * 256 + tid;
            cp_async16(db + u * 16,        (const char*)W_hi_g + gb + u * 16);
            cp_async16(db + 8192 + u * 16, (const char*)W_lo_g + gb + u * 16);
        }
        CP_COMMIT();
    }

    // ---- load x0, stage into A buf0; load x1 into regs ----
    float4 xa[2][2], xn[2][2];
    #pragma unroll
    for (int i = 0; i < 2; i++) {
        const float4* p = (const float4*)&x[(size_t)(row0 + cr[i]) * EDIM + cc8[i] * 8];
        xa[i][0] = p[0]; xa[i][1] = p[1];
    }
    #pragma unroll
    for (int i = 0; i < 2; i++) {
        uint4 H, L;
        cvtpair(xa[i][0].x, xa[i][0].y, H.x, L.x);
        cvtpair(xa[i][0].z, xa[i][0].w, H.y, L.y);
        cvtpair(xa[i][1].x, xa[i][1].y, H.z, L.z);
        cvtpair(xa[i][1].z, xa[i][1].w, H.w, L.w);
        uint32_t off = (uint32_t)(cr[i] * 128 + ((cc8[i] ^ (cr[i] & 7)) << 4));
        *(uint4*)(sm + SM_A + off) = H;
        *(uint4*)(sm + SM_A + 8192 + off) = L;
    }
    #pragma unroll
    for (int i = 0; i < 2; i++) {
        const float4* p = (const float4*)&x[(size_t)(row0 + cr[i]) * EDIM + 64 + cc8[i] * 8];
        xa[i][0] = p[0]; xa[i][1] = p[1];
    }
    CP_WAIT(1);          // B0 complete (own copies); barrier publishes all
    __syncthreads();

    // ================= mainloop: ONE sync per chunk =================
    #pragma unroll 1
    for (int c = 0; c < 16; c++) {
        const uint32_t aRd = sA + (c & 1) * 16384;
        const uint32_t bRd = sB + (c % 3) * 16384;

        // start x_{c+2} LDG early
        if (c + 2 < 16) {
            #pragma unroll
            for (int i = 0; i < 2; i++) {
                const float4* p = (const float4*)&x[(size_t)(row0 + cr[i]) * EDIM + (c + 2) * 64 + cc8[i] * 8];
                xn[i][0] = p[0]; xn[i][1] = p[1];
            }
        }
        // cp.async B_{c+2}; commit EVERY iter (empty groups keep count uniform)
        if (c + 2 < 16) {
            uint32_t db = sB + ((c + 2) % 3) * 16384;
            size_t gb = (size_t)(c + 2) * 8192;
            #pragma unroll
            for (int i = 0; i < 2; i++) {
                int u = i * 256 + tid;
                cp_async16(db + u * 16,        (const char*)W_hi_g + gb + u * 16);
                cp_async16(db + 8192 + u * 16, (const char*)W_lo_g + gb + u * 16);
            }
        }
        CP_COMMIT();

        // stage x_{c+1} (in xa) into the other A buffer
        if (c < 15) {
            char* dh = sm + SM_A + ((c + 1) & 1) * 16384;
            #pragma unroll
            for (int i = 0; i < 2; i++) {
                uint4 H, L;
                cvtpair(xa[i][0].x, xa[i][0].y, H.x, L.x);
                cvtpair(xa[i][0].z, xa[i][0].w, H.y, L.y);
                cvtpair(xa[i][1].x, xa[i][1].y, H.z, L.z);
                cvtpair(xa[i][1].z, xa[i][1].w, H.w, L.w);
                uint32_t off = (uint32_t)(cr[i] * 128 + ((cc8[i] ^ (cr[i] & 7)) << 4));
                *(uint4*)(dh + off) = H;
                *(uint4*)(dh + 8192 + off) = L;
            }
        }
        if (c + 2 < 16) {
            #pragma unroll
            for (int i = 0; i < 2; i++) { xa[i][0] = xn[i][0]; xa[i][1] = xn[i][1]; }
        }

        // MMA phase: 4 k16-groups x 2 tile-pairs x 3 passes (B via ldsm x4)
        #pragma unroll
        for (int gk = 0; gk < 4; gk++) {
            uint32_t ah4[4], al4[4];
            uint32_t aoff = (uint32_t)(arow * 128 + (((2 * gk + achunk_add) ^ l7) << 4));
            ldsm_x4(ah4[0], ah4[1], ah4[2], ah4[3], aRd + aoff);
            ldsm_x4(al4[0], al4[1], al4[2], al4[3], aRd + 8192 + aoff);
            #pragma unroll
            for (int p = 0; p < 2; p++) {
                const int tile = ((p == 0) ? 2 * h : 4 + 2 * h) + bt_add;
                uint32_t boff = (uint32_t)((8 * tile + l7) * 128 + (((2 * gk + bk_half) ^ l7) << 4));
                uint32_t bh[4], bl[4];
                ldsm_x4(bh[0], bh[1], bh[2], bh[3], bRd + boff);
                ldsm_x4(bl[0], bl[1], bl[2], bl[3], bRd + 8192 + boff);
                mma_bf16(acc[2 * p],     ah4, bh[0], bh[1]);
                mma_bf16(acc[2 * p + 1], ah4, bh[2], bh[3]);
                mma_bf16(acc[2 * p],     ah4, bl[0], bl[1]);
                mma_bf16(acc[2 * p + 1], ah4, bl[2], bl[3]);
                mma_bf16(acc[2 * p],     al4, bh[0], bh[1]);
                mma_bf16(acc[2 * p + 1], al4, bh[2], bh[3]);
            }
        }
        CP_WAIT(1);      // B_{c+1} complete before the barrier publishes it
        __syncthreads();
    }

    // ============ exchange: q,k (+bias) -> zq/zk smem (alias A) ============
    const int g = lid >> 2, t = lid & 3;
    {
        const int lr0 = mwrow + g, lr1 = lr0 + 8;
        #pragma unroll
        for (int jj = 0; jj < 2; jj++) {          // q tiles
            int col = 16 * h + 8 * jj + 2 * t;
            float2 b2 = *(const float2*)&bq[col];
            *(float2*)&zq[lr0 * 32 + col] = make_float2(acc[jj][0] + b2.x, acc[jj][1] + b2.y);
            *(float2*)&zq[lr1 * 32 + col] = make_float2(acc[jj][2] + b2.x, acc[jj][3] + b2.y);
        }
        #pragma unroll
        for (int jj = 2; jj < 4; jj++) {          // k tiles
            int col = 16 * h + 8 * (jj - 2) + 2 * t;
            float2 b2 = *(const float2*)&bk[col];
            *(float2*)&zk[lr0 * 32 + col] = make_float2(acc[jj][0] + b2.x, acc[jj][1] + b2.y);
            *(float2*)&zk[lr1 * 32 + col] = make_float2(acc[jj][2] + b2.x, acc[jj][3] + b2.y);
        }
    }
    // convert w into smem over dead B region (1 row per thread)
    {
        const int row = tid;
        #pragma unroll
        for (int j = 0; j < 8; j++) {
            float4 v = *(const float4*)&w[(size_t)row * DHEAD + 4 * j];
            uint32_t h0, l0, h1, l1;
            cvtpair(v.x, v.y, h0, l0);
            cvtpair(v.z, v.w, h1, l1);
            wsh[row * 20 + 2 * j]     = h0;
            wsh[row * 20 + 2 * j + 1] = h1;
            wsl[row * 20 + 2 * j]     = l0;
            wsl[row * 20 + 2 * j + 1] = l1;
        }
    }
    __syncthreads();

    // ============ rebuild feat A-frags + s from zq/zk ============
    const int lr0 = mwrow + g, lr1 = lr0 + 8;
    uint32_t ah[2][4], al[2][4];
    float s0 = 0.f, s1 = 0.f;
    #pragma unroll
    for (int kg = 0; kg < 2; kg++) {
        #pragma unroll
        for (int hh = 0; hh < 2; hh++) {
            int col = kg * 16 + hh * 8 + 2 * t;
            float2 q0 = *(const float2*)&zq[lr0 * 32 + col];
            float2 k0 = *(const float2*)&zk[lr0 * 32 + col];
            float2 q1 = *(const float2*)&zq[lr1 * 32 + col];
            float2 k1 = *(const float2*)&zk[lr1 * 32 + col];
            s0 += q0.x * q0.x + q0.y * q0.y + k0.x * k0.x + k0.y * k0.y;
            s1 += q1.x * q1.x + q1.y * q1.y + k1.x * k1.x + k1.y * k1.y;
            cvtpair(q0.x + k0.x, q0.y + k0.y, ah[kg][2 * hh],     al[kg][2 * hh]);
            cvtpair(q1.x + k1.x, q1.y + k1.y, ah[kg][2 * hh + 1], al[kg][2 * hh + 1]);
        }
    }
    s0 += __shfl_xor_sync(0xffffffffu, s0, 1);
    s0 += __shfl_xor_sync(0xffffffffu, s0, 2);
    s1 += __shfl_xor_sync(0xffffffffu, s1, 1);
    s1 += __shfl_xor_sync(0xffffffffu, s1, 2);
    s0 *= 0.5f;
    s1 *= 0.5f;

    // ============ phase 2: features (n-half per warp) ============
    const int r0 = row0 + lr0;
    const int nhalf = h * 128;
    #pragma unroll 4
    for (int j = 0; j < 16; j++) {
        const int nb = nhalf + 8 * j;
        const uint32_t* bhp = &wsh[(nb + g) * 20 + t];
        const uint32_t* blp = &wsl[(nb + g) * 20 + t];
        uint32_t bh0 = bhp[0], bh1 = bhp[4], bh2 = bhp[8], bh3 = bhp[12];
        uint32_t bl0 = blp[0], bl1 = blp[4], bl2 = blp[8], bl3 = blp[12];

        float c[4] = {0.f, 0.f, 0.f, 0.f};
        mma_bf16(c, ah[0], bh0, bh1);   // hi*hi
        mma_bf16(c, ah[1], bh2, bh3);
        mma_bf16(c, ah[0], bl0, bl1);   // hi*lo
        mma_bf16(c, ah[1], bl2, bl3);
        mma_bf16(c, al[0], bh0, bh1);   // lo*hi
        mma_bf16(c, al[1], bh2, bh3);

        float r00 = 0.5f * (__expf(c[0] - s0) + __expf(-c[0] - s0));
        float r01 = 0.5f * (__expf(c[1] - s0) + __expf(-c[1] - s0));
        float r10 = 0.5f * (__expf(c[2] - s1) + __expf(-c[2] - s1));
        float r11 = 0.5f * (__expf(c[3] - s1) + __expf(-c[3] - s1));
        *(float2*)&out[(size_t)r0 * MFEAT + nb + 2 * t]       = make_float2(r00, r01);
        *(float2*)&out[(size_t)(r0 + 8) * MFEAT + nb + 2 * t] = make_float2(r10, r11);
    }
}

extern "C" void kernel_launch(void* const* d_in, const int* in_sizes, int n_in,
                              void* d_out, int out_size)
{
    const float* x  = (const float*)d_in[0];
    const float* Wq = (const float*)d_in[1];
    const float* bq = (const float*)d_in[2];
    const float* Wk = (const float*)d_in[3];
    const float* bk = (const float*)d_in[4];
    // d_in[5], d_in[6] = Wv, bv: unused (reference discards v)
    const float* w  = (const float*)d_in[7];
    float* out = (float*)d_out;

    static bool attr_set = false;   // idempotent host-side attribute
    if (!attr_set) {
        cudaFuncSetAttribute(fused_kernel, cudaFuncAttributeMaxDynamicSharedMemorySize, SMEM_SZ);
        attr_set = true;
    }
    wprep_kernel<<<64, 256>>>(Wq, Wk);
    fused_kernel<<<N_TOK / 64, 256, SMEM_SZ>>>(x, bq, bk, w, out);
}

// round 13
// speedup vs baseline: 3.6190x; 1.0460x over previous
#include <cuda_runtime.h>
#include <cuda_bf16.h>
#include <cstdint>

#define N_TOK   16384      // B*T
#define EDIM    1024
#define DHEAD   32
#define MFEAT   256

// ---------------- scratch (__device__ globals; no allocation) ----------------
// W combined [64 n][1024 k] bf16 hi/lo, per 64-K chunk, 16B-chunk swizzled:
// element (c, n, kk) at [c*4096 + n*64 + ((kk/8 ^ (n&7))*8) + (kk&7)]
__device__ __nv_bfloat16 W_hi_g[16 * 64 * 64];
__device__ __nv_bfloat16 W_lo_g[16 * 64 * 64];

__device__ __forceinline__ uint32_t smem_u32(const void* p) {
    uint32_t a;
    asm("{ .reg .u64 t; cvta.to.shared.u64 t, %1; cvt.u32.u64 %0, t; }" : "=r"(a) : "l"(p));
    return a;
}
__device__ __forceinline__ void ldsm_x4(uint32_t& r0, uint32_t& r1, uint32_t& r2, uint32_t& r3, uint32_t a) {
    asm volatile("ldmatrix.sync.aligned.m8n8.x4.shared.b16 {%0,%1,%2,%3}, [%4];"
                 : "=r"(r0), "=r"(r1), "=r"(r2), "=r"(r3) : "r"(a));
}
__device__ __forceinline__ void ldsm_x2(uint32_t& r0, uint32_t& r1, uint32_t a) {
    asm volatile("ldmatrix.sync.aligned.m8n8.x2.shared.b16 {%0,%1}, [%2];"
                 : "=r"(r0), "=r"(r1) : "r"(a));
}
__device__ __forceinline__ void mma_bf16(float* c, const uint32_t* a, uint32_t b0, uint32_t b1) {
    asm volatile("mma.sync.aligned.m16n8k16.row.col.f32.bf16.bf16.f32 "
                 "{%0,%1,%2,%3}, {%4,%5,%6,%7}, {%8,%9}, {%0,%1,%2,%3};"
                 : "+f"(c[0]), "+f"(c[1]), "+f"(c[2]), "+f"(c[3])
                 : "r"(a[0]), "r"(a[1]), "r"(a[2]), "r"(a[3]), "r"(b0), "r"(b1));
}
__device__ __forceinline__ void cvtpair(float x, float y, uint32_t& h, uint32_t& l) {
    __nv_bfloat162 hh = __float22bfloat162_rn(make_float2(x, y));
    float2 f = __bfloat1622float2(hh);
    __nv_bfloat162 ll = __float22bfloat162_rn(make_float2(x - f.x, y - f.y));
    h = *(uint32_t*)&hh;
    l = *(uint32_t*)&ll;
}
__device__ __forceinline__ void cp_async16(uint32_t dst, const void* src) {
    asm volatile("cp.async.cg.shared.global [%0], [%1], 16;" :: "r"(dst), "l"(src) : "memory");
}
#define CP_COMMIT()  asm volatile("cp.async.commit_group;" ::: "memory")
#define CP_WAIT(n)   asm volatile("cp.async.wait_group %0;" :: "n"(n) : "memory")

// ---------------- kernel 0: W -> bf16 hi/lo, chunk-swizzled ------------------
__global__ __launch_bounds__(256) void wprep_kernel(
    const float* __restrict__ Wq, const float* __restrict__ Wk)
{
    int idx  = blockIdx.x * 256 + threadIdx.x;   // 0..16383
    int c    = idx >> 10;
    int rest = idx & 1023;
    int kk   = rest >> 4;
    int ng   = rest & 15;                        // group of 4 n
    int k    = c * 64 + kk;
    float4 v = (ng < 8) ? ((const float4*)Wq)[k * 8 + ng]
                        : ((const float4*)Wk)[k * 8 + (ng - 8)];
    const float* vp = &v.x;
    #pragma unroll
    for (int e = 0; e < 4; e++) {
        int n = ng * 4 + e;
        float f = vp[e];
        __nv_bfloat16 h = __float2bfloat16(f);
        __nv_bfloat16 l = __float2bfloat16(f - __bfloat162float(h));
        int pos = c * 4096 + n * 64 + (((kk >> 3) ^ (n & 7)) << 3) + (kk & 7);
        W_hi_g[pos] = h;
        W_lo_g[pos] = l;
    }
}

// ---------------- fused kernel: projection GEMM + features ------------------
// 256 thr / 8 warps, M=128 tokens/CTA, grid 128.
// Warp = (mw = (wid>>1)*32 : two 16-row subtiles, h = wid&1 : dim half).
// B fragments loaded ONCE per n-tile, consumed by BOTH m-subtiles
// (1.33 LDSM-wavefronts/MMA vs 2.0 before — attacks the L1tex bound).
// R11-style pipeline: single A buffer, 2 syncs/chunk, B double-buffer cp.async.
#define SM_A      0              // hi 16K + lo 16K = 32KB   (phase2: zq/zk)
#define SM_B      32768          // 2 bufs x (hi 8K + lo 8K) = 32KB
#define SM_WSH    32768          // phase2 alias over B+: uint32[256*20]
#define SM_WSL    53248
#define SMEM_SZ   73728

__global__ __launch_bounds__(256, 1) void fused_kernel(
    const float* __restrict__ x,
    const float* __restrict__ bq, const float* __restrict__ bk,
    const float* __restrict__ w, float* __restrict__ out)
{
    extern __shared__ __align__(16) char sm[];
    float* zq = (float*)(sm + SM_A);            // phase2 alias (A dead) 16KB
    float* zk = (float*)(sm + SM_A + 16384);    // 16KB
    uint32_t* wsh = (uint32_t*)(sm + SM_WSH);   // phase2 alias (B dead)
    uint32_t* wsl = (uint32_t*)(sm + SM_WSL);

    const int tid = threadIdx.x;
    const int wid = tid >> 5, lid = tid & 31;
    const int row0 = blockIdx.x * 128;

    const uint32_t smb = smem_u32(sm);
    const uint32_t sA = smb + SM_A;              // hi at +0, lo at +16384
    const uint32_t sB = smb + SM_B;

    const int mw = (wid >> 1) * 32;       // warp's 32-row block (CTA-local)
    const int h  = wid & 1;               // dim-half

    float acc[2][4][4];                   // [m-subtile][tile: q{2h,2h+1},k{4+2h,5+2h}]
    #pragma unroll
    for (int ms = 0; ms < 2; ms++)
        #pragma unroll
        for (int j = 0; j < 4; j++)
            acc[ms][j][0] = acc[ms][j][1] = acc[ms][j][2] = acc[ms][j][3] = 0.f;

    // x staging: 1024 8-float groups over 256 threads -> 4 groups/thread
    int cr[4], cc8[4];
    #pragma unroll
    for (int i = 0; i < 4; i++) {
        int idx = i * 256 + tid;
        cr[i]  = idx >> 3;                // row 0..127
        cc8[i] = idx & 7;
    }
    // ldmatrix lane geometry
    const int i4   = lid >> 3;
    const int arow_off = ((i4 & 1) << 3) + (lid & 7);
    const int l7   = lid & 7;
    const int achunk_add = i4 >> 1;
    const int b_i  = (lid >> 3) & 1;

    // ---- prologue: cp.async B0; LDG x0 ----
    #pragma unroll
    for (int i = 0; i < 2; i++) {
        int u = i * 256 + tid;
        cp_async16(sB + u * 16,        (const char*)W_hi_g + u * 16);
        cp_async16(sB + 8192 + u * 16, (const char*)W_lo_g + u * 16);
    }
    CP_COMMIT();

    float4 xa[4][2];
    #pragma unroll
    for (int i = 0; i < 4; i++) {
        const float4* p = (const float4*)&x[(size_t)(row0 + cr[i]) * EDIM + cc8[i] * 8];
        xa[i][0] = p[0]; xa[i][1] = p[1];
    }

    // ================= mainloop =================
    #pragma unroll 1
    for (int c = 0; c < 16; c++) {
        // stage x_c (in xa) into A smem (swizzled bf16 hi/lo)
        #pragma unroll
        for (int i = 0; i < 4; i++) {
            uint4 H, L;
            cvtpair(xa[i][0].x, xa[i][0].y, H.x, L.x);
            cvtpair(xa[i][0].z, xa[i][0].w, H.y, L.y);
            cvtpair(xa[i][1].x, xa[i][1].y, H.z, L.z);
            cvtpair(xa[i][1].z, xa[i][1].w, H.w, L.w);
            uint32_t off = (uint32_t)(cr[i] * 128 + ((cc8[i] ^ (cr[i] & 7)) << 4));
            *(uint4*)(sm + SM_A + off) = H;
            *(uint4*)(sm + SM_A + 16384 + off) = L;
        }
        if (c < 15) {
            // LDG x_{c+1} into xa (WAR on staging resolved by scheduler)
            #pragma unroll
            for (int i = 0; i < 4; i++) {
                const float4* p = (const float4*)&x[(size_t)(row0 + cr[i]) * EDIM + (c + 1) * 64 + cc8[i] * 8];
                xa[i][0] = p[0]; xa[i][1] = p[1];
            }
            // cp.async B_{c+1} into other buf
            const uint32_t db = sB + ((c + 1) & 1) * 16384;
            const size_t gb = (size_t)(c + 1) * 8192;
            #pragma unroll
            for (int i = 0; i < 2; i++) {
                int u = i * 256 + tid;
                cp_async16(db + u * 16,        (const char*)W_hi_g + gb + u * 16);
                cp_async16(db + 8192 + u * 16, (const char*)W_lo_g + gb + u * 16);
            }
            CP_COMMIT();
            CP_WAIT(1);      // B_c complete (own copies); barrier publishes all
        } else {
            CP_WAIT(0);
        }
        __syncthreads();

        // MMA phase: 4 k16-groups x 4 n-tiles x 2 m-subtiles x 3 passes
        const uint32_t sBh = sB + (c & 1) * 16384;
        const uint32_t sBl = sBh + 8192;
        #pragma unroll
        for (int gk = 0; gk < 4; gk++) {
            uint32_t ah4[2][4], al4[2][4];
            #pragma unroll
            for (int ms = 0; ms < 2; ms++) {
                uint32_t aoff = (uint32_t)((mw + 16 * ms + arow_off) * 128
                               + (((2 * gk + achunk_add) ^ l7) << 4));
                ldsm_x4(ah4[ms][0], ah4[ms][1], ah4[ms][2], ah4[ms][3], sA + aoff);
                ldsm_x4(al4[ms][0], al4[ms][1], al4[ms][2], al4[ms][3], sA + 16384 + aoff);
            }
            #pragma unroll
            for (int jj = 0; jj < 4; jj++) {
                const int tile = (jj < 2) ? (2 * h + jj) : (2 + 2 * h + jj);
                uint32_t boff = (uint32_t)((8 * tile + l7) * 128 + (((2 * gk + b_i) ^ l7) << 4));
                uint32_t bh0, bh1, bl0, bl1;
                ldsm_x2(bh0, bh1, sBh + boff);
                ldsm_x2(bl0, bl1, sBl + boff);
                #pragma unroll
                for (int ms = 0; ms < 2; ms++) {
                    mma_bf16(acc[ms][jj], ah4[ms], bh0, bh1);
                    mma_bf16(acc[ms][jj], ah4[ms], bl0, bl1);
                    mma_bf16(acc[ms][jj], al4[ms], bh0, bh1);
                }
            }
        }
        __syncthreads();
    }

    // ============ exchange: q,k (+bias) -> zq/zk smem (alias A) ============
    const int g = lid >> 2, t = lid & 3;
    #pragma unroll
    for (int ms = 0; ms < 2; ms++) {
        const int lr0 = mw + 16 * ms + g, lr1 = lr0 + 8;
        #pragma unroll
        for (int jj = 0; jj < 2; jj++) {          // q tiles
            int col = 16 * h + 8 * jj + 2 * t;
            float2 b2 = *(const float2*)&bq[col];
            *(float2*)&zq[lr0 * 32 + col] = make_float2(acc[ms][jj][0] + b2.x, acc[ms][jj][1] + b2.y);
            *(float2*)&zq[lr1 * 32 + col] = make_float2(acc[ms][jj][2] + b2.x, acc[ms][jj][3] + b2.y);
        }
        #pragma unroll
        for (int jj = 2; jj < 4; jj++) {          // k tiles
            int col = 16 * h + 8 * (jj - 2) + 2 * t;
            float2 b2 = *(const float2*)&bk[col];
            *(float2*)&zk[lr0 * 32 + col] = make_float2(acc[ms][jj][0] + b2.x, acc[ms][jj][1] + b2.y);
            *(float2*)&zk[lr1 * 32 + col] = make_float2(acc[ms][jj][2] + b2.x, acc[ms][jj][3] + b2.y);
        }
    }
    // convert w into smem over dead B region (1 row per thread)
    {
        const int row = tid;
        #pragma unroll
        for (int j = 0; j < 8; j++) {
            float4 v = *(const float4*)&w[(size_t)row * DHEAD + 4 * j];
            uint32_t h0, l0, h1, l1;
            cvtpair(v.x, v.y, h0, l0);
            cvtpair(v.z, v.w, h1, l1);
            wsh[row * 20 + 2 * j]     = h0;
            wsh[row * 20 + 2 * j + 1] = h1;
            wsl[row * 20 + 2 * j]     = l0;
            wsl[row * 20 + 2 * j + 1] = l1;
        }
    }
    __syncthreads();

    // ============ rebuild feat A-frags + s from zq/zk ============
    // phase-2 ownership: warp wid -> rows wid*16 .. wid*16+16
    const int lr0 = wid * 16 + g, lr1 = lr0 + 8;
    uint32_t ah[2][4], al[2][4];
    float s0 = 0.f, s1 = 0.f;
    #pragma unroll
    for (int kg = 0; kg < 2; kg++) {
        #pragma unroll
        for (int hh = 0; hh < 2; hh++) {
            int col = kg * 16 + hh * 8 + 2 * t;
            float2 q0 = *(const float2*)&zq[lr0 * 32 + col];
            float2 k0 = *(const float2*)&zk[lr0 * 32 + col];
            float2 q1 = *(const float2*)&zq[lr1 * 32 + col];
            float2 k1 = *(const float2*)&zk[lr1 * 32 + col];
            s0 += q0.x * q0.x + q0.y * q0.y + k0.x * k0.x + k0.y * k0.y;
            s1 += q1.x * q1.x + q1.y * q1.y + k1.x * k1.x + k1.y * k1.y;
            cvtpair(q0.x + k0.x, q0.y + k0.y, ah[kg][2 * hh],     al[kg][2 * hh]);
            cvtpair(q1.x + k1.x, q1.y + k1.y, ah[kg][2 * hh + 1], al[kg][2 * hh + 1]);
        }
    }
    s0 += __shfl_xor_sync(0xffffffffu, s0, 1);
    s0 += __shfl_xor_sync(0xffffffffu, s0, 2);
    s1 += __shfl_xor_sync(0xffffffffu, s1, 1);
    s1 += __shfl_xor_sync(0xffffffffu, s1, 2);
    s0 *= 0.5f;
    s1 *= 0.5f;

    // ============ phase 2: features (all 256 per warp) ============
    const int r0 = row0 + lr0;
    #pragma unroll 4
    for (int j = 0; j < 32; j++) {
        const int nb = 8 * j;
        const uint32_t* bhp = &wsh[(nb + g) * 20 + t];
        const uint32_t* blp = &wsl[(nb + g) * 20 + t];
        uint32_t bh0 = bhp[0], bh1 = bhp[4], bh2 = bhp[8], bh3 = bhp[12];
        uint32_t bl0 = blp[0], bl1 = blp[4], bl2 = blp[8], bl3 = blp[12];

        float c[4] = {0.f, 0.f, 0.f, 0.f};
        mma_bf16(c, ah[0], bh0, bh1);   // hi*hi
        mma_bf16(c, ah[1], bh2, bh3);
        mma_bf16(c, ah[0], bl0, bl1);   // hi*lo
        mma_bf16(c, ah[1], bl2, bl3);
        mma_bf16(c, al[0], bh0, bh1);   // lo*hi
        mma_bf16(c, al[1], bh2, bh3);

        float r00 = 0.5f * (__expf(c[0] - s0) + __expf(-c[0] - s0));
        float r01 = 0.5f * (__expf(c[1] - s0) + __expf(-c[1] - s0));
        float r10 = 0.5f * (__expf(c[2] - s1) + __expf(-c[2] - s1));
        float r11 = 0.5f * (__expf(c[3] - s1) + __expf(-c[3] - s1));
        *(float2*)&out[(size_t)r0 * MFEAT + nb + 2 * t]       = make_float2(r00, r01);
        *(float2*)&out[(size_t)(r0 + 8) * MFEAT + nb + 2 * t] = make_float2(r10, r11);
    }
}

extern "C" void kernel_launch(void* const* d_in, const int* in_sizes, int n_in,
                              void* d_out, int out_size)
{
    const float* x  = (const float*)d_in[0];
    const float* Wq = (const float*)d_in[1];
    const float* bq = (const float*)d_in[2];
    const float* Wk = (const float*)d_in[3];
    const float* bk = (const float*)d_in[4];
    // d_in[5], d_in[6] = Wv, bv: unused (reference discards v)
    const float* w  = (const float*)d_in[7];
    float* out = (float*)d_out;

    static bool attr_set = false;   // idempotent host-side attribute
    if (!attr_set) {
        cudaFuncSetAttribute(fused_kernel, cudaFuncAttributeMaxDynamicSharedMemorySize, SMEM_SZ);
        attr_set = true;
    }
    wprep_kernel<<<64, 256>>>(Wq, Wk);
    fused_kernel<<<N_TOK / 128, 256, SMEM_SZ>>>(x, bq, bk, w, out);
}

// round 14
// speedup vs baseline: 3.6845x; 1.0181x over previous
#include <cuda_runtime.h>
#include <cuda_bf16.h>
#include <cstdint>

#define N_TOK   16384      // B*T
#define EDIM    1024
#define DHEAD   32
#define MFEAT   256

// ---------------- scratch (__device__ globals; no allocation) ----------------
// W combined [64 n][1024 k] bf16 hi/lo, per 64-K chunk, 16B-chunk swizzled:
// element (c, n, kk) at [c*4096 + n*64 + ((kk/8 ^ (n&7))*8) + (kk&7)]
__device__ __nv_bfloat16 W_hi_g[16 * 64 * 64];
__device__ __nv_bfloat16 W_lo_g[16 * 64 * 64];

__device__ __forceinline__ uint32_t smem_u32(const void* p) {
    uint32_t a;
    asm("{ .reg .u64 t; cvta.to.shared.u64 t, %1; cvt.u32.u64 %0, t; }" : "=r"(a) : "l"(p));
    return a;
}
__device__ __forceinline__ void ldsm_x4(uint32_t& r0, uint32_t& r1, uint32_t& r2, uint32_t& r3, uint32_t a) {
    asm volatile("ldmatrix.sync.aligned.m8n8.x4.shared.b16 {%0,%1,%2,%3}, [%4];"
                 : "=r"(r0), "=r"(r1), "=r"(r2), "=r"(r3) : "r"(a));
}
__device__ __forceinline__ void ldsm_x2(uint32_t& r0, uint32_t& r1, uint32_t a) {
    asm volatile("ldmatrix.sync.aligned.m8n8.x2.shared.b16 {%0,%1}, [%2];"
                 : "=r"(r0), "=r"(r1) : "r"(a));
}
__device__ __forceinline__ void mma_bf16(float* c, const uint32_t* a, uint32_t b0, uint32_t b1) {
    asm volatile("mma.sync.aligned.m16n8k16.row.col.f32.bf16.bf16.f32 "
                 "{%0,%1,%2,%3}, {%4,%5,%6,%7}, {%8,%9}, {%0,%1,%2,%3};"
                 : "+f"(c[0]), "+f"(c[1]), "+f"(c[2]), "+f"(c[3])
                 : "r"(a[0]), "r"(a[1]), "r"(a[2]), "r"(a[3]), "r"(b0), "r"(b1));
}
__device__ __forceinline__ void cvtpair(float x, float y, uint32_t& h, uint32_t& l) {
    __nv_bfloat162 hh = __float22bfloat162_rn(make_float2(x, y));
    float2 f = __bfloat1622float2(hh);
    __nv_bfloat162 ll = __float22bfloat162_rn(make_float2(x - f.x, y - f.y));
    h = *(uint32_t*)&hh;
    l = *(uint32_t*)&ll;
}
__device__ __forceinline__ void cp_async16(uint32_t dst, const void* src) {
    asm volatile("cp.async.cg.shared.global [%0], [%1], 16;" :: "r"(dst), "l"(src) : "memory");
}
#define CP_COMMIT()  asm volatile("cp.async.commit_group;" ::: "memory")
#define CP_WAIT(n)   asm volatile("cp.async.wait_group %0;" :: "n"(n) : "memory")
#define BAR_SET(id)  asm volatile("bar.sync %0, %1;" :: "r"(id), "r"(256) : "memory")

// ---------------- kernel 0: W -> bf16 hi/lo, chunk-swizzled ------------------
__global__ __launch_bounds__(256) void wprep_kernel(
    const float* __restrict__ Wq, const float* __restrict__ Wk)
{
    int idx  = blockIdx.x * 256 + threadIdx.x;   // 0..16383
    int c    = idx >> 10;
    int rest = idx & 1023;
    int kk   = rest >> 4;
    int ng   = rest & 15;                        // group of 4 n
    int k    = c * 64 + kk;
    float4 v = (ng < 8) ? ((const float4*)Wq)[k * 8 + ng]
                        : ((const float4*)Wk)[k * 8 + (ng - 8)];
    const float* vp = &v.x;
    #pragma unroll
    for (int e = 0; e < 4; e++) {
        int n = ng * 4 + e;
        float f = vp[e];
        __nv_bfloat16 h = __float2bfloat16(f);
        __nv_bfloat16 l = __float2bfloat16(f - __bfloat162float(h));
        int pos = c * 4096 + n * 64 + (((kk >> 3) ^ (n & 7)) << 3) + (kk & 7);
        W_hi_g[pos] = h;
        W_lo_g[pos] = l;
    }
}

// ---------------- fused kernel: in-CTA split-K projection + features --------
// 512 thr / 16 warps, M=128 tokens/CTA, grid 128.
// Set s = warps 8s..8s+7 handles K half [s*512, s*512+512) with its own
// A/B smem + named barrier -> 4 warps/SMSP latency hiding at 1.33 wf/MMA.
// Exchange: partial q/k summed via smem (zqA+zqB+bias); feat on 16 warps.
#define SM_A      0              // set s: s*32768 (hi +0, lo +16384) = 64KB
#define SM_B      65536          // set s: 65536 + s*32768, 2 bufs x 16K = 64KB
#define SM_WSH    65536          // phase2 alias over B: uint32[256*20]
#define SM_WSL    86016
#define SMEM_SZ   131072

__global__ __launch_bounds__(512, 1) void fused_kernel(
    const float* __restrict__ x,
    const float* __restrict__ bq, const float* __restrict__ bk,
    const float* __restrict__ w, float* __restrict__ out)
{
    extern __shared__ __align__(16) char sm[];
    // phase-2 aliases
    float* zqA = (float*)(sm);               // 128x32 f32 partial q, set 0
    float* zkA = (float*)(sm + 16384);
    float* zqB = (float*)(sm + 32768);       // set 1
    float* zkB = (float*)(sm + 49152);
    uint32_t* wsh = (uint32_t*)(sm + SM_WSH);
    uint32_t* wsl = (uint32_t*)(sm + SM_WSL);

    const int tid = threadIdx.x;
    const int lid = tid & 31;
    const int set = tid >> 8;              // 0 or 1
    const int ts  = tid & 255;             // thread id within set
    const int wid_s = ts >> 5;             // warp id within set 0..7
    const int row0 = blockIdx.x * 128;
    const int kbase = set * 512;

    const uint32_t smb = smem_u32(sm);
    const uint32_t sA = smb + set * 32768;           // hi +0, lo +16384
    const uint32_t sBset = smb + SM_B + set * 32768; // buf b: +b*16384

    char* Aset = sm + set * 32768;

    const int mw = (wid_s >> 1) * 32;      // warp's 32-row block
    const int h  = wid_s & 1;              // dim-half

    float acc[2][4][4];
    #pragma unroll
    for (int ms = 0; ms < 2; ms++)
        #pragma unroll
        for (int j = 0; j < 4; j++)
            acc[ms][j][0] = acc[ms][j][1] = acc[ms][j][2] = acc[ms][j][3] = 0.f;

    // x staging: 1024 8-float groups over 256 set-threads -> 4 groups/thread
    int cr[4], cc8[4];
    #pragma unroll
    for (int i = 0; i < 4; i++) {
        int idx = i * 256 + ts;
        cr[i]  = idx >> 3;                 // row 0..127
        cc8[i] = idx & 7;
    }
    // ldmatrix lane geometry
    const int i4   = lid >> 3;
    const int arow_off = ((i4 & 1) << 3) + (lid & 7);
    const int l7   = lid & 7;
    const int achunk_add = i4 >> 1;
    const int b_i  = (lid >> 3) & 1;

    // ---- prologue: cp.async B chunk (set*8) into buf 0 ----
    {
        size_t gb = (size_t)(set * 8) * 8192;
        #pragma unroll
        for (int i = 0; i < 2; i++) {
            int u = i * 256 + ts;
            cp_async16(sBset + u * 16,        (const char*)W_hi_g + gb + u * 16);
            cp_async16(sBset + 8192 + u * 16, (const char*)W_lo_g + gb + u * 16);
        }
        CP_COMMIT();
    }

    // ================= mainloop: 8 chunks of K=64 =================
    #pragma unroll 1
    for (int c = 0; c < 8; c++) {
        // LDG + convert + stage x chunk (cross-warp overlap hides latency)
        #pragma unroll
        for (int i = 0; i < 4; i++) {
            const float4* p = (const float4*)&x[(size_t)(row0 + cr[i]) * EDIM + kbase + c * 64 + cc8[i] * 8];
            float4 v0 = p[0], v1 = p[1];
            uint4 H, L;
            cvtpair(v0.x, v0.y, H.x, L.x);
            cvtpair(v0.z, v0.w, H.y, L.y);
            cvtpair(v1.x, v1.y, H.z, L.z);
            cvtpair(v1.z, v1.w, H.w, L.w);
            uint32_t off = (uint32_t)(cr[i] * 128 + ((cc8[i] ^ (cr[i] & 7)) << 4));
            *(uint4*)(Aset + off) = H;
            *(uint4*)(Aset + 16384 + off) = L;
        }
        if (c < 7) {
            const uint32_t db = sBset + ((c + 1) & 1) * 16384;
            const size_t gb = (size_t)(set * 8 + c + 1) * 8192;
            #pragma unroll
            for (int i = 0; i < 2; i++) {
                int u = i * 256 + ts;
                cp_async16(db + u * 16,        (const char*)W_hi_g + gb + u * 16);
                cp_async16(db + 8192 + u * 16, (const char*)W_lo_g + gb + u * 16);
            }
            CP_COMMIT();
            CP_WAIT(1);      // B_c arrived (own copies); barrier publishes all
        } else {
            CP_WAIT(0);
        }
        BAR_SET(1 + set);

        // MMA: 4 k16-groups x 4 n-tiles x 2 m-subtiles x 3 passes
        const uint32_t sBh = sBset + (c & 1) * 16384;
        const uint32_t sBl = sBh + 8192;
        #pragma unroll
        for (int gk = 0; gk < 4; gk++) {
            uint32_t ah4[2][4], al4[2][4];
            #pragma unroll
            for (int ms = 0; ms < 2; ms++) {
                uint32_t aoff = (uint32_t)((mw + 16 * ms + arow_off) * 128
                               + (((2 * gk + achunk_add) ^ l7) << 4));
                ldsm_x4(ah4[ms][0], ah4[ms][1], ah4[ms][2], ah4[ms][3], sA + aoff);
                ldsm_x4(al4[ms][0], al4[ms][1], al4[ms][2], al4[ms][3], sA + 16384 + aoff);
            }
            #pragma unroll
            for (int jj = 0; jj < 4; jj++) {
                const int tile = (jj < 2) ? (2 * h + jj) : (2 + 2 * h + jj);
                uint32_t boff = (uint32_t)((8 * tile + l7) * 128 + (((2 * gk + b_i) ^ l7) << 4));
                uint32_t bh0, bh1, bl0, bl1;
                ldsm_x2(bh0, bh1, sBh + boff);
                ldsm_x2(bl0, bl1, sBl + boff);
                #pragma unroll
                for (int ms = 0; ms < 2; ms++) {
                    mma_bf16(acc[ms][jj], ah4[ms], bh0, bh1);
                    mma_bf16(acc[ms][jj], ah4[ms], bl0, bl1);
                    mma_bf16(acc[ms][jj], al4[ms], bh0, bh1);
                }
            }
        }
        BAR_SET(1 + set);
    }

    // ============ exchange: partial q,k (NO bias) -> own zq/zk region ========
    const int g = lid >> 2, t = lid & 3;
    {
        float* zq = (float*)(sm + set * 32768);
        float* zk = (float*)(sm + set * 32768 + 16384);
        #pragma unroll
        for (int ms = 0; ms < 2; ms++) {
            const int lr0 = mw + 16 * ms + g, lr1 = lr0 + 8;
            #pragma unroll
            for (int jj = 0; jj < 2; jj++) {      // q tiles
                int col = 16 * h + 8 * jj + 2 * t;
                *(float2*)&zq[lr0 * 32 + col] = make_float2(acc[ms][jj][0], acc[ms][jj][1]);
                *(float2*)&zq[lr1 * 32 + col] = make_float2(acc[ms][jj][2], acc[ms][jj][3]);
            }
            #pragma unroll
            for (int jj = 2; jj < 4; jj++) {      // k tiles
                int col = 16 * h + 8 * (jj - 2) + 2 * t;
                *(float2*)&zk[lr0 * 32 + col] = make_float2(acc[ms][jj][0], acc[ms][jj][1]);
                *(float2*)&zk[lr1 * 32 + col] = make_float2(acc[ms][jj][2], acc[ms][jj][3]);
            }
        }
    }
    __syncthreads();
    // w tables over dead B region (threads 0-255, one row each)
    if (tid < 256) {
        const int row = tid;
        #pragma unroll
        for (int j = 0; j < 8; j++) {
            float4 v = *(const float4*)&w[(size_t)row * DHEAD + 4 * j];
            uint32_t h0, l0, h1, l1;
            cvtpair(v.x, v.y, h0, l0);
            cvtpair(v.z, v.w, h1, l1);
            wsh[row * 20 + 2 * j]     = h0;
            wsh[row * 20 + 2 * j + 1] = h1;
            wsl[row * 20 + 2 * j]     = l0;
            wsl[row * 20 + 2 * j + 1] = l1;
        }
    }
    __syncthreads();

    // ============ rebuild feat A-frags + s (sum partials + bias) ============
    // 16 warps: rows ((wid&7)*16), n-half (wid>>3)*128
    const int fw = tid >> 5;
    const int lr0 = (fw & 7) * 16 + g, lr1 = lr0 + 8;
    const int nhalf = (fw >> 3) * 128;
    uint32_t ah[2][4], al[2][4];
    float s0 = 0.f, s1 = 0.f;
    #pragma unroll
    for (int kg = 0; kg < 2; kg++) {
        #pragma unroll
        for (int hh = 0; hh < 2; hh++) {
            int col = kg * 16 + hh * 8 + 2 * t;
            float2 bq2 = *(const float2*)&bq[col];
            float2 bk2 = *(const float2*)&bk[col];
            float2 qa0 = *(const float2*)&zqA[lr0 * 32 + col];
            float2 qb0 = *(const float2*)&zqB[lr0 * 32 + col];
            float2 ka0 = *(const float2*)&zkA[lr0 * 32 + col];
            float2 kb0 = *(const float2*)&zkB[lr0 * 32 + col];
            float2 qa1 = *(const float2*)&zqA[lr1 * 32 + col];
            float2 qb1 = *(const float2*)&zqB[lr1 * 32 + col];
            float2 ka1 = *(const float2*)&zkA[lr1 * 32 + col];
            float2 kb1 = *(const float2*)&zkB[lr1 * 32 + col];
            float q00 = qa0.x + qb0.x + bq2.x, q01 = qa0.y + qb0.y + bq2.y;
            float k00 = ka0.x + kb0.x + bk2.x, k01 = ka0.y + kb0.y + bk2.y;
            float q10 = qa1.x + qb1.x + bq2.x, q11 = qa1.y + qb1.y + bq2.y;
            float k10 = ka1.x + kb1.x + bk2.x, k11 = ka1.y + kb1.y + bk2.y;
            s0 += q00 * q00 + q01 * q01 + k00 * k00 + k01 * k01;
            s1 += q10 * q10 + q11 * q11 + k10 * k10 + k11 * k11;
            cvtpair(q00 + k00, q01 + k01, ah[kg][2 * hh],     al[kg][2 * hh]);
            cvtpair(q10 + k10, q11 + k11, ah[kg][2 * hh + 1], al[kg][2 * hh + 1]);
        }
    }
    s0 += __shfl_xor_sync(0xffffffffu, s0, 1);
    s0 += __shfl_xor_sync(0xffffffffu, s0, 2);
    s1 += __shfl_xor_sync(0xffffffffu, s1, 1);
    s1 += __shfl_xor_sync(0xffffffffu, s1, 2);
    s0 *= 0.5f;
    s1 *= 0.5f;

    // ============ phase 2: features (16 n-tiles per warp) ============
    const int r0 = row0 + lr0;
    #pragma unroll 4
    for (int j = 0; j < 16; j++) {
        const int nb = nhalf + 8 * j;
        const uint32_t* bhp = &wsh[(nb + g) * 20 + t];
        const uint32_t* blp = &wsl[(nb + g) * 20 + t];
        uint32_t bh0 = bhp[0], bh1 = bhp[4], bh2 = bhp[8], bh3 = bhp[12];
        uint32_t bl0 = blp[0], bl1 = blp[4], bl2 = blp[8], bl3 = blp[12];

        float c[4] = {0.f, 0.f, 0.f, 0.f};
        mma_bf16(c, ah[0], bh0, bh1);   // hi*hi
        mma_bf16(c, ah[1], bh2, bh3);
        mma_bf16(c, ah[0], bl0, bl1);   // hi*lo
        mma_bf16(c, ah[1], bl2, bl3);
        mma_bf16(c, al[0], bh0, bh1);   // lo*hi
        mma_bf16(c, al[1], bh2, bh3);

        float r00 = 0.5f * (__expf(c[0] - s0) + __expf(-c[0] - s0));
        float r01 = 0.5f * (__expf(c[1] - s0) + __expf(-c[1] - s0));
        float r10 = 0.5f * (__expf(c[2] - s1) + __expf(-c[2] - s1));
        float r11 = 0.5f * (__expf(c[3] - s1) + __expf(-c[3] - s1));
        *(float2*)&out[(size_t)r0 * MFEAT + nb + 2 * t]       = make_float2(r00, r01);
        *(float2*)&out[(size_t)(r0 + 8) * MFEAT + nb + 2 * t] = make_float2(r10, r11);
    }
}

extern "C" void kernel_launch(void* const* d_in, const int* in_sizes, int n_in,
                              void* d_out, int out_size)
{
    const float* x  = (const float*)d_in[0];
    const float* Wq = (const float*)d_in[1];
    const float* bq = (const float*)d_in[2];
    const float* Wk = (const float*)d_in[3];
    const float* bk = (const float*)d_in[4];
    // d_in[5], d_in[6] = Wv, bv: unused (reference discards v)
    const float* w  = (const float*)d_in[7];
    float* out = (float*)d_out;

    static bool attr_set = false;   // idempotent host-side attribute
    if (!attr_set) {
        cudaFuncSetAttribute(fused_kernel, cudaFuncAttributeMaxDynamicSharedMemorySize, SMEM_SZ);
        attr_set = true;
    }
    wprep_kernel<<<64, 256>>>(Wq, Wk);
    fused_kernel<<<N_TOK / 128, 512, SMEM_SZ>>>(x, bq, bk, w, out);
}